// round 8
// baseline (speedup 1.0000x reference)
#include <cuda_runtime.h>
#include <cuda_fp16.h>
#include <math.h>
#include <stdint.h>

// Problem constants
constexpr int cB  = 8;
constexpr int cSQ = 512;
constexpr int cSK = 1024;
constexpr int cD  = 1024;
constexpr int cH  = 16;
constexpr int cDK = 64;
constexpr int cF  = 4096;

// ---------------------------------------------------------------------------
// Scratch (device globals; no allocations allowed)
// ---------------------------------------------------------------------------
__device__ float g_bufQ [(size_t)cB*cSQ*cD];
__device__ float g_bufK [(size_t)cB*cSK*cD];
__device__ float g_bufV [(size_t)cB*cSK*cD];
__device__ float g_bufS [(size_t)cB*cH*cSQ*cSQ];
__device__ float g_bufC [(size_t)cB*cSQ*cD];
__device__ float g_bufO [(size_t)cB*cSQ*cD];
__device__ float g_bufX1[(size_t)cB*cSQ*cD];
__device__ float g_bufX2[(size_t)cB*cSQ*cD];
__device__ float g_bufF [(size_t)cB*cSQ*cF];

// ---------------------------------------------------------------------------
// helpers
// ---------------------------------------------------------------------------
__device__ __forceinline__ void mma_f16(float c[4],
    uint32_t a0, uint32_t a1, uint32_t a2, uint32_t a3,
    uint32_t b0, uint32_t b1)
{
    asm volatile(
        "mma.sync.aligned.m16n8k16.row.col.f32.f16.f16.f32 "
        "{%0,%1,%2,%3}, {%4,%5,%6,%7}, {%8,%9}, {%0,%1,%2,%3};"
        : "+f"(c[0]), "+f"(c[1]), "+f"(c[2]), "+f"(c[3])
        : "r"(a0), "r"(a1), "r"(a2), "r"(a3), "r"(b0), "r"(b1));
}

__device__ __forceinline__ uint32_t h2u(__half2 h) {
    return *reinterpret_cast<uint32_t*>(&h);
}

__device__ __forceinline__ uint32_t smem_u32(const void* p) {
    uint32_t a;
    asm("{ .reg .u64 t; cvta.to.shared.u64 t, %1; cvt.u32.u64 %0, t; }"
        : "=r"(a) : "l"(p));
    return a;
}

__device__ __forceinline__ void ldmatrix_x4(
    uint32_t& r0, uint32_t& r1, uint32_t& r2, uint32_t& r3, uint32_t addr)
{
    asm volatile("ldmatrix.sync.aligned.m8n8.x4.shared.b16 {%0,%1,%2,%3}, [%4];"
        : "=r"(r0), "=r"(r1), "=r"(r2), "=r"(r3) : "r"(addr));
}

// ---------------------------------------------------------------------------
// fp16 GEMM v2: C[M,N] = A[M,K] @ W[K,N] + bias (+ReLU), f32 accumulate.
// 128x128 block, 256 threads / 8 warps (2x4), warp tile 64x32, k-step 32,
// double-buffered smem, ldmatrix.x4 for A frags, k-pair-packed half2 B.
// As2: [m][k2] stride 20 half2 (80B rows, 16B aligned, conflict-free ldmatrix)
// Bs2: [k2][n] stride 136 half2 (frag banks 8*tig+g, conflict-free LDS.32)
// ---------------------------------------------------------------------------
template<bool RELU>
__global__ __launch_bounds__(256, 2) void gemm_fp16_v2(
    const float* __restrict__ A, const float* __restrict__ W,
    const float* __restrict__ bias, float* __restrict__ C,
    int M, int N, int K)
{
    __shared__ __align__(16) __half2 As2[2][128 * 20];
    __shared__ __align__(16) __half2 Bs2[2][16 * 136];

    const int tid  = threadIdx.x;
    const int bx   = blockIdx.x, by = blockIdx.y;
    const int warp = tid >> 5, lane = tid & 31;
    const int g = lane >> 2, tig = lane & 3;
    const int wm = warp >> 2;      // 0..1 -> 64 rows
    const int wn = warp & 3;       // 0..3 -> 32 cols

    // A loader: row ar, half2 k-offset ac8 (0 or 8)
    const int ar  = tid >> 1;
    const int ac8 = (tid & 1) * 8;
    const float* Asrc = A + (size_t)(by*128 + ar)*K + ac8*2;

    // B loader: k-pair bk2 (0..15), n-offset bn (0..120)
    const int bk2 = tid >> 4;
    const int bn  = (tid & 15) * 8;
    const float* Bsrc0 = W + (size_t)(2*bk2)*N + bx*128 + bn;
    const float* Bsrc1 = Bsrc0 + N;

    const int nk = K >> 5;

    uint4 aR[2], bR[2];
    auto ldg = [&](int kt) {
        const float* ap = Asrc + kt*32;
        float4 v0 = *(const float4*)(ap);
        float4 v1 = *(const float4*)(ap + 4);
        float4 v2 = *(const float4*)(ap + 8);
        float4 v3 = *(const float4*)(ap + 12);
        aR[0] = make_uint4(h2u(__floats2half2_rn(v0.x, v0.y)), h2u(__floats2half2_rn(v0.z, v0.w)),
                           h2u(__floats2half2_rn(v1.x, v1.y)), h2u(__floats2half2_rn(v1.z, v1.w)));
        aR[1] = make_uint4(h2u(__floats2half2_rn(v2.x, v2.y)), h2u(__floats2half2_rn(v2.z, v2.w)),
                           h2u(__floats2half2_rn(v3.x, v3.y)), h2u(__floats2half2_rn(v3.z, v3.w)));
        const float* bp0 = Bsrc0 + (size_t)kt*32*N;
        const float* bp1 = Bsrc1 + (size_t)kt*32*N;
        float4 w0 = *(const float4*)(bp0), w1 = *(const float4*)(bp0 + 4);
        float4 x0 = *(const float4*)(bp1), x1 = *(const float4*)(bp1 + 4);
        bR[0] = make_uint4(h2u(__floats2half2_rn(w0.x, x0.x)), h2u(__floats2half2_rn(w0.y, x0.y)),
                           h2u(__floats2half2_rn(w0.z, x0.z)), h2u(__floats2half2_rn(w0.w, x0.w)));
        bR[1] = make_uint4(h2u(__floats2half2_rn(w1.x, x1.x)), h2u(__floats2half2_rn(w1.y, x1.y)),
                           h2u(__floats2half2_rn(w1.z, x1.z)), h2u(__floats2half2_rn(w1.w, x1.w)));
    };
    auto sts = [&](int s) {
        *(uint4*)&As2[s][ar*20 + ac8]      = aR[0];
        *(uint4*)&As2[s][ar*20 + ac8 + 4]  = aR[1];
        *(uint4*)&Bs2[s][bk2*136 + bn]     = bR[0];
        *(uint4*)&Bs2[s][bk2*136 + bn + 4] = bR[1];
    };

    // ldmatrix per-lane base: lanes 0-7 rows 0-7 (k lo), 8-15 rows 8-15 (k lo),
    // 16-23 rows 0-7 (k hi), 24-31 rows 8-15 (k hi)
    const int lrow  = lane & 15;
    const int khalf = (lane >> 4) & 1;
    const uint32_t a_base = smem_u32(&As2[0][0])
                          + ((uint32_t)(wm*64 + lrow)*20 + khalf*4) * 4;
    constexpr uint32_t A_STAGE = 128 * 20 * 4;

    float acc[4][4][4] = {};

    ldg(0); sts(0);
    __syncthreads();

    for (int kt = 0; kt < nk; kt++) {
        if (kt + 1 < nk) ldg(kt + 1);

        const int s = kt & 1;
        const __half2* bs = Bs2[s];
        const uint32_t abase = a_base + s * A_STAGE;

#pragma unroll
        for (int kk = 0; kk < 2; kk++) {          // two k16 halves of the k32 tile
            uint32_t af[4][4];
#pragma unroll
            for (int mt = 0; mt < 4; mt++)
                ldmatrix_x4(af[mt][0], af[mt][1], af[mt][2], af[mt][3],
                            abase + (uint32_t)(mt*16*20 + kk*8) * 4);
            const int kb = kk * 8;
            uint32_t bf[4][2];
#pragma unroll
            for (int nt = 0; nt < 4; nt++) {
                int n = wn*32 + nt*8 + g;
                bf[nt][0] = *(const uint32_t*)&bs[(kb + tig)*136 + n];
                bf[nt][1] = *(const uint32_t*)&bs[(kb + 4 + tig)*136 + n];
            }
#pragma unroll
            for (int mt = 0; mt < 4; mt++)
#pragma unroll
                for (int nt = 0; nt < 4; nt++)
                    mma_f16(acc[mt][nt], af[mt][0], af[mt][1], af[mt][2], af[mt][3],
                            bf[nt][0], bf[nt][1]);
        }

        if (kt + 1 < nk) sts((kt + 1) & 1);
        __syncthreads();
    }

#pragma unroll
    for (int mt = 0; mt < 4; mt++) {
#pragma unroll
        for (int nt = 0; nt < 4; nt++) {
            int row0 = by*128 + wm*64 + mt*16 + g;
            int col  = bx*128 + wn*32 + nt*8 + 2*tig;
            float b0 = bias[col], b1 = bias[col + 1];
            float2 v0 = { acc[mt][nt][0] + b0, acc[mt][nt][1] + b1 };
            float2 v1 = { acc[mt][nt][2] + b0, acc[mt][nt][3] + b1 };
            if (RELU) {
                v0.x = fmaxf(v0.x, 0.f); v0.y = fmaxf(v0.y, 0.f);
                v1.x = fmaxf(v1.x, 0.f); v1.y = fmaxf(v1.y, 0.f);
            }
            *(float2*)&C[(size_t)row0*N + col]       = v0;
            *(float2*)&C[(size_t)(row0 + 8)*N + col] = v1;
        }
    }
}

// ---------------------------------------------------------------------------
// QK^T via fp16 mma. Block = 64 q x 64 k. grid = (sk/64, SQ/64, B*H).
// Qs2/Ks2: [row][d2] half2 stride 36 (frag banks 4g+tig; conflict-free).
// ---------------------------------------------------------------------------
__global__ __launch_bounds__(256) void qk_f16_kernel(
    const float* __restrict__ Q, const float* __restrict__ Km,
    float* __restrict__ S, const int* __restrict__ kvmask,
    int sk, int causal, float scale)
{
    __shared__ __align__(16) __half2 Qs2[64 * 36];
    __shared__ __align__(16) __half2 Ks2[64 * 36];
    __shared__ int msk[64];

    const int bh = blockIdx.z;
    const int b  = bh >> 4, h = bh & 15;
    const int q0 = blockIdx.y * 64;
    const int k0 = blockIdx.x * 64;
    const int tid  = threadIdx.x;
    const int warp = tid >> 5, lane = tid & 31;
    const int g = lane >> 2, tig = lane & 3;
    const int wm = warp >> 2;
    const int wn = warp & 3;

    if (causal && k0 > q0 + 63) {
        float4 ninf = { -INFINITY, -INFINITY, -INFINITY, -INFINITY };
#pragma unroll
        for (int it = 0; it < 4; it++) {
            int idx = tid + it * 256;
            int r = idx >> 4, c4 = (idx & 15) * 4;
            *(float4*)(S + ((size_t)bh*cSQ + q0 + r)*sk + k0 + c4) = ninf;
        }
        return;
    }

    const float* Qbase = Q  + ((size_t)b*cSQ + q0)*cD + h*cDK;
    const float* Kbase = Km + ((size_t)b*sk  + k0)*cD + h*cDK;
    {
        const int r = tid >> 2, c = (tid & 3) * 16;
        const float* qp = Qbase + (size_t)r*cD + c;
        float4 v0 = *(const float4*)(qp),     v1 = *(const float4*)(qp + 4);
        float4 v2 = *(const float4*)(qp + 8), v3 = *(const float4*)(qp + 12);
        *(uint4*)&Qs2[r*36 + (tid&3)*8] = make_uint4(
            h2u(__floats2half2_rn(v0.x, v0.y)), h2u(__floats2half2_rn(v0.z, v0.w)),
            h2u(__floats2half2_rn(v1.x, v1.y)), h2u(__floats2half2_rn(v1.z, v1.w)));
        *(uint4*)&Qs2[r*36 + (tid&3)*8 + 4] = make_uint4(
            h2u(__floats2half2_rn(v2.x, v2.y)), h2u(__floats2half2_rn(v2.z, v2.w)),
            h2u(__floats2half2_rn(v3.x, v3.y)), h2u(__floats2half2_rn(v3.z, v3.w)));
        const float* kp = Kbase + (size_t)r*cD + c;
        float4 w0 = *(const float4*)(kp),     w1 = *(const float4*)(kp + 4);
        float4 w2 = *(const float4*)(kp + 8), w3 = *(const float4*)(kp + 12);
        *(uint4*)&Ks2[r*36 + (tid&3)*8] = make_uint4(
            h2u(__floats2half2_rn(w0.x, w0.y)), h2u(__floats2half2_rn(w0.z, w0.w)),
            h2u(__floats2half2_rn(w1.x, w1.y)), h2u(__floats2half2_rn(w1.z, w1.w)));
        *(uint4*)&Ks2[r*36 + (tid&3)*8 + 4] = make_uint4(
            h2u(__floats2half2_rn(w2.x, w2.y)), h2u(__floats2half2_rn(w2.z, w2.w)),
            h2u(__floats2half2_rn(w3.x, w3.y)), h2u(__floats2half2_rn(w3.z, w3.w)));
    }
    if (kvmask && tid < 64) msk[tid] = kvmask[b*sk + k0 + tid];
    __syncthreads();

    float acc[2][2][4] = {};
#pragma unroll
    for (int kk2 = 0; kk2 < 32; kk2 += 8) {   // half2 index, 16 halves/step
        uint32_t af[2][4];
#pragma unroll
        for (int mt = 0; mt < 2; mt++) {
            int r0 = wm*32 + mt*16 + g;
            af[mt][0] = *(const uint32_t*)&Qs2[r0*36 + kk2 + tig];
            af[mt][1] = *(const uint32_t*)&Qs2[(r0 + 8)*36 + kk2 + tig];
            af[mt][2] = *(const uint32_t*)&Qs2[r0*36 + kk2 + 4 + tig];
            af[mt][3] = *(const uint32_t*)&Qs2[(r0 + 8)*36 + kk2 + 4 + tig];
        }
        uint32_t bf[2][2];
#pragma unroll
        for (int nt = 0; nt < 2; nt++) {
            int n = wn*16 + nt*8 + g;
            bf[nt][0] = *(const uint32_t*)&Ks2[n*36 + kk2 + tig];
            bf[nt][1] = *(const uint32_t*)&Ks2[n*36 + kk2 + 4 + tig];
        }
#pragma unroll
        for (int mt = 0; mt < 2; mt++)
#pragma unroll
            for (int nt = 0; nt < 2; nt++)
                mma_f16(acc[mt][nt], af[mt][0], af[mt][1], af[mt][2], af[mt][3],
                        bf[nt][0], bf[nt][1]);
    }

#pragma unroll
    for (int mt = 0; mt < 2; mt++) {
#pragma unroll
        for (int nt = 0; nt < 2; nt++) {
            int qrow = q0 + wm*32 + mt*16 + g;
            int kl   = wn*16 + nt*8 + 2*tig;
            int kcol = k0 + kl;
            bool m0 = kvmask && msk[kl] == 0;
            bool m1 = kvmask && msk[kl + 1] == 0;
#pragma unroll
            for (int rr = 0; rr < 2; rr++) {
                int q = qrow + rr*8;
                float v0 = acc[mt][nt][rr*2 + 0] * scale;
                float v1 = acc[mt][nt][rr*2 + 1] * scale;
                if ((causal && kcol     > q) || m0) v0 = -INFINITY;
                if ((causal && kcol + 1 > q) || m1) v1 = -INFINITY;
                float2 v = { v0, v1 };
                *(float2*)&S[((size_t)bh*cSQ + q)*sk + kcol] = v;
            }
        }
    }
}

// ---------------------------------------------------------------------------
// A @ V via fp16 mma. Block = 64 q x 64 d (one head). grid = (SQ/64, B*H).
// Ps2: [q][k2] stride 20. Vs2: [k2][d] stride 72 (k-pair packed).
// ---------------------------------------------------------------------------
__global__ __launch_bounds__(256) void av_f16_kernel(
    const float* __restrict__ P, const float* __restrict__ V,
    float* __restrict__ O, int sk, int causal)
{
    __shared__ __align__(16) __half2 Ps2[64 * 20];
    __shared__ __align__(16) __half2 Vs2[16 * 72];

    const int bh = blockIdx.y;
    const int b  = bh >> 4, h = bh & 15;
    const int q0 = blockIdx.x * 64;
    const int tid  = threadIdx.x;
    const int warp = tid >> 5, lane = tid & 31;
    const int g = lane >> 2, tig = lane & 3;
    const int wm = warp >> 2;
    const int wn = warp & 3;

    const float* Pbase = P + ((size_t)bh*cSQ + q0)*sk;
    const float* Vbase = V + ((size_t)b*sk)*cD + h*cDK;

    float acc[2][2][4] = {};
    const int kend = causal ? (q0 + 64) : sk;

    const int pr = tid >> 2, pc = (tid & 3) * 8;      // P: row, k-offset
    const int vk2 = tid >> 4, vd = (tid & 15) * 4;    // V: k-pair, d-offset

    for (int k0 = 0; k0 < kend; k0 += 32) {
        {
            const float* pp = Pbase + (size_t)pr*sk + k0 + pc;
            float4 v0 = *(const float4*)(pp), v1 = *(const float4*)(pp + 4);
            *(uint4*)&Ps2[pr*20 + (tid&3)*4] = make_uint4(
                h2u(__floats2half2_rn(v0.x, v0.y)), h2u(__floats2half2_rn(v0.z, v0.w)),
                h2u(__floats2half2_rn(v1.x, v1.y)), h2u(__floats2half2_rn(v1.z, v1.w)));
            const float* vp0 = Vbase + (size_t)(k0 + 2*vk2)*cD + vd;
            const float* vp1 = vp0 + cD;
            float4 w0 = *(const float4*)(vp0);
            float4 w1 = *(const float4*)(vp1);
            *(uint4*)&Vs2[vk2*72 + vd] = make_uint4(
                h2u(__floats2half2_rn(w0.x, w1.x)), h2u(__floats2half2_rn(w0.y, w1.y)),
                h2u(__floats2half2_rn(w0.z, w1.z)), h2u(__floats2half2_rn(w0.w, w1.w)));
        }
        __syncthreads();

#pragma unroll
        for (int kb = 0; kb < 16; kb += 8) {
            uint32_t af[2][4];
#pragma unroll
            for (int mt = 0; mt < 2; mt++) {
                int r0 = wm*32 + mt*16 + g;
                af[mt][0] = *(const uint32_t*)&Ps2[r0*20 + kb + tig];
                af[mt][1] = *(const uint32_t*)&Ps2[(r0 + 8)*20 + kb + tig];
                af[mt][2] = *(const uint32_t*)&Ps2[r0*20 + kb + 4 + tig];
                af[mt][3] = *(const uint32_t*)&Ps2[(r0 + 8)*20 + kb + 4 + tig];
            }
            uint32_t bf[2][2];
#pragma unroll
            for (int nt = 0; nt < 2; nt++) {
                int n = wn*16 + nt*8 + g;
                bf[nt][0] = *(const uint32_t*)&Vs2[(kb + tig)*72 + n];
                bf[nt][1] = *(const uint32_t*)&Vs2[(kb + 4 + tig)*72 + n];
            }
#pragma unroll
            for (int mt = 0; mt < 2; mt++)
#pragma unroll
                for (int nt = 0; nt < 2; nt++)
                    mma_f16(acc[mt][nt], af[mt][0], af[mt][1], af[mt][2], af[mt][3],
                            bf[nt][0], bf[nt][1]);
        }
        __syncthreads();
    }

#pragma unroll
    for (int mt = 0; mt < 2; mt++) {
#pragma unroll
        for (int nt = 0; nt < 2; nt++) {
            int qrow = q0 + wm*32 + mt*16 + g;
            int d    = wn*16 + nt*8 + 2*tig;
#pragma unroll
            for (int rr = 0; rr < 2; rr++) {
                size_t row = (size_t)b*cSQ + qrow + rr*8;
                float2 v = { acc[mt][nt][rr*2 + 0], acc[mt][nt][rr*2 + 1] };
                *(float2*)&O[row*cD + h*cDK + d] = v;
            }
        }
    }
}

// ---------------------------------------------------------------------------
// Register-resident row softmax. One block (256 threads) per row.
// ---------------------------------------------------------------------------
template<int VEC>
__global__ __launch_bounds__(256) void softmax_reg_kernel(float* __restrict__ S)
{
    __shared__ float redm[8];
    __shared__ float reds[8];
    float* p = S + (size_t)blockIdx.x * (256 * VEC);
    const int t = threadIdx.x;
    const int warp = t >> 5, lane = t & 31;

    float v[VEC];
#pragma unroll
    for (int i = 0; i < VEC; i++) v[i] = p[t*VEC + i];

    float m = v[0];
#pragma unroll
    for (int i = 1; i < VEC; i++) m = fmaxf(m, v[i]);
#pragma unroll
    for (int off = 16; off > 0; off >>= 1)
        m = fmaxf(m, __shfl_xor_sync(0xffffffffu, m, off));
    if (lane == 0) redm[warp] = m;
    __syncthreads();
    float bm = redm[0];
#pragma unroll
    for (int i = 1; i < 8; i++) bm = fmaxf(bm, redm[i]);

    float s = 0.f;
#pragma unroll
    for (int i = 0; i < VEC; i++) {
        v[i] = __expf(v[i] - bm);
        s += v[i];
    }
#pragma unroll
    for (int off = 16; off > 0; off >>= 1)
        s += __shfl_xor_sync(0xffffffffu, s, off);
    if (lane == 0) reds[warp] = s;
    __syncthreads();
    float bs = reds[0];
#pragma unroll
    for (int i = 1; i < 8; i++) bs += reds[i];

    float inv = 1.0f / bs;
#pragma unroll
    for (int i = 0; i < VEC; i++) p[t*VEC + i] = v[i] * inv;
}

// ---------------------------------------------------------------------------
// out = LayerNorm(X + R) * g + b over last dim (D=1024). One block per row.
// ---------------------------------------------------------------------------
__global__ __launch_bounds__(256) void ln_residual_kernel(
    const float* __restrict__ X, const float* __restrict__ R,
    const float* __restrict__ g, const float* __restrict__ be,
    float* __restrict__ out)
{
    __shared__ float red[256];
    const size_t row = blockIdx.x;
    const int t = threadIdx.x;
    const float* xr = X + row*cD;
    const float* rr = R + row*cD;

    float v[4]; float s = 0.f;
#pragma unroll
    for (int i = 0; i < 4; i++) { v[i] = xr[t + i*256] + rr[t + i*256]; s += v[i]; }
    red[t] = s; __syncthreads();
    for (int k = 128; k > 0; k >>= 1) { if (t < k) red[t] += red[t+k]; __syncthreads(); }
    float mu = red[0] * (1.0f / cD); __syncthreads();

    float vs = 0.f;
#pragma unroll
    for (int i = 0; i < 4; i++) { float d = v[i] - mu; vs += d*d; }
    red[t] = vs; __syncthreads();
    for (int k = 128; k > 0; k >>= 1) { if (t < k) red[t] += red[t+k]; __syncthreads(); }
    float inv = rsqrtf(red[0] * (1.0f / cD) + 1e-5f);

    float* orow = out + row*cD;
#pragma unroll
    for (int i = 0; i < 4; i++) {
        int c = t + i*256;
        orow[c] = (v[i] - mu) * inv * g[c] + be[c];
    }
}

// ---------------------------------------------------------------------------
// Launch
// ---------------------------------------------------------------------------
extern "C" void kernel_launch(void* const* d_in, const int* in_sizes, int n_in,
                              void* d_out, int out_size)
{
    const float* x        = (const float*)d_in[0];
    const float* enc_o    = (const float*)d_in[1];
    const int*   enc_mask = (const int*)  d_in[2];
    const float* a1_wq = (const float*)d_in[3];
    const float* a1_bq = (const float*)d_in[4];
    const float* a1_wk = (const float*)d_in[5];
    const float* a1_bk = (const float*)d_in[6];
    const float* a1_wv = (const float*)d_in[7];
    const float* a1_bv = (const float*)d_in[8];
    const float* a1_wo = (const float*)d_in[9];
    const float* a1_bo = (const float*)d_in[10];
    const float* a2_wq = (const float*)d_in[11];
    const float* a2_bq = (const float*)d_in[12];
    const float* a2_wk = (const float*)d_in[13];
    const float* a2_bk = (const float*)d_in[14];
    const float* a2_wv = (const float*)d_in[15];
    const float* a2_bv = (const float*)d_in[16];
    const float* a2_wo = (const float*)d_in[17];
    const float* a2_bo = (const float*)d_in[18];
    const float* ff_w1 = (const float*)d_in[19];
    const float* ff_b1 = (const float*)d_in[20];
    const float* ff_w2 = (const float*)d_in[21];
    const float* ff_b2 = (const float*)d_in[22];
    const float* ln1_g = (const float*)d_in[23];
    const float* ln1_b = (const float*)d_in[24];
    const float* ln2_g = (const float*)d_in[25];
    const float* ln2_b = (const float*)d_in[26];
    const float* ln3_g = (const float*)d_in[27];
    const float* ln3_b = (const float*)d_in[28];

    float* out_x    = (float*)d_out;
    float* out_attn = out_x + (size_t)cB*cSQ*cD;

    float *bufQ, *bufK, *bufV, *bufS, *bufC, *bufO, *bufX1, *bufX2, *bufF;
    cudaGetSymbolAddress((void**)&bufQ,  g_bufQ);
    cudaGetSymbolAddress((void**)&bufK,  g_bufK);
    cudaGetSymbolAddress((void**)&bufV,  g_bufV);
    cudaGetSymbolAddress((void**)&bufS,  g_bufS);
    cudaGetSymbolAddress((void**)&bufC,  g_bufC);
    cudaGetSymbolAddress((void**)&bufO,  g_bufO);
    cudaGetSymbolAddress((void**)&bufX1, g_bufX1);
    cudaGetSymbolAddress((void**)&bufX2, g_bufX2);
    cudaGetSymbolAddress((void**)&bufF,  g_bufF);

    const float scale = 0.125f;   // 1/sqrt(64)
    const dim3 blk(256);
    const int M1 = cB * cSQ;      // 4096
    const int M2 = cB * cSK;      // 8192

    // ---- self-attention (causal) ----
    gemm_fp16_v2<false><<<dim3(cD/128, M1/128), blk>>>(x, a1_wq, a1_bq, bufQ, M1, cD, cD);
    gemm_fp16_v2<false><<<dim3(cD/128, M1/128), blk>>>(x, a1_wk, a1_bk, bufK, M1, cD, cD);
    gemm_fp16_v2<false><<<dim3(cD/128, M1/128), blk>>>(x, a1_wv, a1_bv, bufV, M1, cD, cD);
    qk_f16_kernel<<<dim3(cSQ/64, cSQ/64, cB*cH), blk>>>(bufQ, bufK, bufS, nullptr, cSQ, 1, scale);
    softmax_reg_kernel<2><<<cB*cH*cSQ, blk>>>(bufS);
    av_f16_kernel<<<dim3(cSQ/64, cB*cH), blk>>>(bufS, bufV, bufC, cSQ, 1);
    gemm_fp16_v2<false><<<dim3(cD/128, M1/128), blk>>>(bufC, a1_wo, a1_bo, bufO, M1, cD, cD);
    ln_residual_kernel<<<M1, blk>>>(x, bufO, ln1_g, ln1_b, bufX1);

    // ---- cross-attention (kv mask); probs go straight into d_out ----
    gemm_fp16_v2<false><<<dim3(cD/128, M1/128), blk>>>(bufX1, a2_wq, a2_bq, bufQ, M1, cD, cD);
    gemm_fp16_v2<false><<<dim3(cD/128, M2/128), blk>>>(enc_o, a2_wk, a2_bk, bufK, M2, cD, cD);
    gemm_fp16_v2<false><<<dim3(cD/128, M2/128), blk>>>(enc_o, a2_wv, a2_bv, bufV, M2, cD, cD);
    qk_f16_kernel<<<dim3(cSK/64, cSQ/64, cB*cH), blk>>>(bufQ, bufK, out_attn, enc_mask, cSK, 0, scale);
    softmax_reg_kernel<4><<<cB*cH*cSQ, blk>>>(out_attn);
    av_f16_kernel<<<dim3(cSQ/64, cB*cH), blk>>>(out_attn, bufV, bufC, cSK, 0);
    gemm_fp16_v2<false><<<dim3(cD/128, M1/128), blk>>>(bufC, a2_wo, a2_bo, bufO, M1, cD, cD);
    ln_residual_kernel<<<M1, blk>>>(bufX1, bufO, ln2_g, ln2_b, bufX2);

    // ---- feed-forward ----
    gemm_fp16_v2<true ><<<dim3(cF/128, M1/128), blk>>>(bufX2, ff_w1, ff_b1, bufF, M1, cF, cD);
    gemm_fp16_v2<false><<<dim3(cD/128, M1/128), blk>>>(bufF, ff_w2, ff_b2, bufO, M1, cD, cF);
    ln_residual_kernel<<<M1, blk>>>(bufX2, bufO, ln3_g, ln3_b, out_x);
}

// round 10
// speedup vs baseline: 1.0272x; 1.0272x over previous
#include <cuda_runtime.h>
#include <cuda_fp16.h>
#include <math.h>
#include <stdint.h>

// Problem constants
constexpr int cB  = 8;
constexpr int cSQ = 512;
constexpr int cSK = 1024;
constexpr int cD  = 1024;
constexpr int cH  = 16;
constexpr int cDK = 64;
constexpr int cF  = 4096;

// ---------------------------------------------------------------------------
// Scratch (device globals; no allocations allowed)
// ---------------------------------------------------------------------------
__device__ float g_bufQ [(size_t)cB*cSQ*cD];
__device__ float g_bufK [(size_t)cB*cSK*cD];
__device__ float g_bufV [(size_t)cB*cSK*cD];
__device__ float g_bufC [(size_t)cB*cSQ*cD];
__device__ float g_bufO [(size_t)cB*cSQ*cD];
__device__ float g_bufX1[(size_t)cB*cSQ*cD];
__device__ float g_bufX2[(size_t)cB*cSQ*cD];
__device__ float g_bufF [(size_t)cB*cSQ*cF];

// ---------------------------------------------------------------------------
// helpers
// ---------------------------------------------------------------------------
__device__ __forceinline__ void mma_f16(float c[4],
    uint32_t a0, uint32_t a1, uint32_t a2, uint32_t a3,
    uint32_t b0, uint32_t b1)
{
    asm volatile(
        "mma.sync.aligned.m16n8k16.row.col.f32.f16.f16.f32 "
        "{%0,%1,%2,%3}, {%4,%5,%6,%7}, {%8,%9}, {%0,%1,%2,%3};"
        : "+f"(c[0]), "+f"(c[1]), "+f"(c[2]), "+f"(c[3])
        : "r"(a0), "r"(a1), "r"(a2), "r"(a3), "r"(b0), "r"(b1));
}

__device__ __forceinline__ uint32_t h2u(__half2 h) {
    return *reinterpret_cast<uint32_t*>(&h);
}

// ---------------------------------------------------------------------------
// fp16 GEMM (round-6 proven): C[M,N] = A[M,K] @ W[K,N] + bias (+ReLU).
// 128x128 block, 256 threads / 8 warps (2x4), warp tile 64x32, k-step 16.
// ---------------------------------------------------------------------------
template<bool RELU>
__global__ __launch_bounds__(256, 2) void gemm_fp16(
    const float* __restrict__ A, const float* __restrict__ W,
    const float* __restrict__ bias, float* __restrict__ C,
    int M, int N, int K)
{
    __shared__ __half2 As2[128 * 12];
    __shared__ __half2 Bs2[8 * 136];

    const int tid  = threadIdx.x;
    const int bx   = blockIdx.x, by = blockIdx.y;
    const int warp = tid >> 5, lane = tid & 31;
    const int g = lane >> 2, tig = lane & 3;
    const int wm = warp >> 2;
    const int wn = warp & 3;

    const int ar  = tid >> 1;
    const int ac2 = (tid & 1) * 4;
    const float* Asrc = A + (size_t)(by*128 + ar)*K + ac2*2;

    const int bk2 = warp;
    const int bn  = lane * 4;
    const float* Bsrc0 = W + (size_t)(2*bk2    )*N + bx*128 + bn;
    const float* Bsrc1 = W + (size_t)(2*bk2 + 1)*N + bx*128 + bn;

    const int nk = K >> 4;
    float acc[4][4][4] = {};

    float4 pa0 = *(const float4*)(Asrc);
    float4 pa1 = *(const float4*)(Asrc + 4);
    float4 pb0 = *(const float4*)(Bsrc0);
    float4 pb1 = *(const float4*)(Bsrc1);

    for (int kt = 0; kt < nk; kt++) {
        {
            __half2 a0 = __floats2half2_rn(pa0.x, pa0.y);
            __half2 a1 = __floats2half2_rn(pa0.z, pa0.w);
            __half2 a2 = __floats2half2_rn(pa1.x, pa1.y);
            __half2 a3 = __floats2half2_rn(pa1.z, pa1.w);
            *(uint4*)&As2[ar*12 + ac2] = make_uint4(h2u(a0), h2u(a1), h2u(a2), h2u(a3));

            __half2 b0 = __floats2half2_rn(pb0.x, pb1.x);
            __half2 b1 = __floats2half2_rn(pb0.y, pb1.y);
            __half2 b2 = __floats2half2_rn(pb0.z, pb1.z);
            __half2 b3 = __floats2half2_rn(pb0.w, pb1.w);
            *(uint4*)&Bs2[bk2*136 + bn] = make_uint4(h2u(b0), h2u(b1), h2u(b2), h2u(b3));
        }
        __syncthreads();

        if (kt + 1 < nk) {
            const int kn = (kt + 1) << 4;
            pa0 = *(const float4*)(Asrc + kn);
            pa1 = *(const float4*)(Asrc + kn + 4);
            pb0 = *(const float4*)(Bsrc0 + (size_t)kn*N);
            pb1 = *(const float4*)(Bsrc1 + (size_t)kn*N);
        }

        uint32_t af[4][4];
#pragma unroll
        for (int mt = 0; mt < 4; mt++) {
            int r0 = wm*64 + mt*16 + g;
            af[mt][0] = *(uint32_t*)&As2[r0*12 + tig];
            af[mt][1] = *(uint32_t*)&As2[(r0 + 8)*12 + tig];
            af[mt][2] = *(uint32_t*)&As2[r0*12 + 4 + tig];
            af[mt][3] = *(uint32_t*)&As2[(r0 + 8)*12 + 4 + tig];
        }
        uint32_t bf[4][2];
#pragma unroll
        for (int nt = 0; nt < 4; nt++) {
            int n = wn*32 + nt*8 + g;
            bf[nt][0] = *(uint32_t*)&Bs2[tig*136 + n];
            bf[nt][1] = *(uint32_t*)&Bs2[(4 + tig)*136 + n];
        }
#pragma unroll
        for (int mt = 0; mt < 4; mt++)
#pragma unroll
            for (int nt = 0; nt < 4; nt++)
                mma_f16(acc[mt][nt], af[mt][0], af[mt][1], af[mt][2], af[mt][3],
                        bf[nt][0], bf[nt][1]);
        __syncthreads();
    }

#pragma unroll
    for (int mt = 0; mt < 4; mt++) {
#pragma unroll
        for (int nt = 0; nt < 4; nt++) {
            int row0 = by*128 + wm*64 + mt*16 + g;
            int col  = bx*128 + wn*32 + nt*8 + 2*tig;
            float b0 = bias[col], b1 = bias[col + 1];
            float2 v0 = { acc[mt][nt][0] + b0, acc[mt][nt][1] + b1 };
            float2 v1 = { acc[mt][nt][2] + b0, acc[mt][nt][3] + b1 };
            if (RELU) {
                v0.x = fmaxf(v0.x, 0.f); v0.y = fmaxf(v0.y, 0.f);
                v1.x = fmaxf(v1.x, 0.f); v1.y = fmaxf(v1.y, 0.f);
            }
            *(float2*)&C[(size_t)row0*N + col]       = v0;
            *(float2*)&C[(size_t)(row0 + 8)*N + col] = v1;
        }
    }
}

// ---------------------------------------------------------------------------
// Fused attention: qk^T -> softmax -> (optional P writeout) -> @V.
// Block = 64 q-rows x full k-extent, one (b,h). S kept fp16 in smem.
// CAUSAL: kend = q0+64, no P writeout. !CAUSAL: kend = sk, kv-mask, P -> gmem.
// Ssm stride: SSTR half2 (== 4 mod 32 -> conflict-free mma frag access).
// Softmax: 4 lanes per row, strided loops (NO power-of-2 assumption on kext2).
// ---------------------------------------------------------------------------
template<bool CAUSAL, bool WRITE_P>
__global__ __launch_bounds__(256) void fused_attn_kernel(
    const float* __restrict__ Q, const float* __restrict__ K,
    const float* __restrict__ V, const int* __restrict__ kvmask,
    float* __restrict__ P, float* __restrict__ O, int sk, float scale)
{
    constexpr int SSTR = CAUSAL ? 260 : 516;    // half2 stride, ==4 mod 32
    constexpr int OFF_S   = 0;
    constexpr int OFF_Q   = OFF_S + 64*SSTR*4;
    constexpr int OFF_K   = OFF_Q + 64*36*4;
    constexpr int OFF_V   = OFF_K + 64*36*4;
    constexpr int OFF_MSK = OFF_V + 16*72*4;

    extern __shared__ char smraw[];
    __half2* Ssm = (__half2*)(smraw + OFF_S);
    __half2* Qs2 = (__half2*)(smraw + OFF_Q);
    __half2* Ks2 = (__half2*)(smraw + OFF_K);
    __half2* Vs2 = (__half2*)(smraw + OFF_V);
    int*     msk = (int*)    (smraw + OFF_MSK);

    const int bh = blockIdx.y;
    const int b  = bh >> 4, h = bh & 15;
    const int q0 = blockIdx.x * 64;
    const int tid  = threadIdx.x;
    const int warp = tid >> 5, lane = tid & 31;
    const int g = lane >> 2, tig = lane & 3;
    const int wm = warp >> 2;     // 0..1 -> 32 q
    const int wn = warp & 3;      // 0..3 -> 16 cols

    const int kend = CAUSAL ? (q0 + 64) : sk;

    // ---- load Q tile (64 x 64) as half2 [row][d2] stride 36 ----
    {
        const int r = tid >> 2, cq = tid & 3;
        const float* qp = Q + ((size_t)b*cSQ + q0 + r)*cD + h*cDK + cq*16;
        float4 v0 = *(const float4*)(qp),     v1 = *(const float4*)(qp + 4);
        float4 v2 = *(const float4*)(qp + 8), v3 = *(const float4*)(qp + 12);
        *(uint4*)&Qs2[r*36 + cq*8] = make_uint4(
            h2u(__floats2half2_rn(v0.x, v0.y)), h2u(__floats2half2_rn(v0.z, v0.w)),
            h2u(__floats2half2_rn(v1.x, v1.y)), h2u(__floats2half2_rn(v1.z, v1.w)));
        *(uint4*)&Qs2[r*36 + cq*8 + 4] = make_uint4(
            h2u(__floats2half2_rn(v2.x, v2.y)), h2u(__floats2half2_rn(v2.z, v2.w)),
            h2u(__floats2half2_rn(v3.x, v3.y)), h2u(__floats2half2_rn(v3.z, v3.w)));
    }
    if (!CAUSAL)
        for (int i = tid; i < sk; i += 256) msk[i] = kvmask[b*sk + i];

    // ---- QK^T phase: stream K tiles, S -> smem fp16 ----
    const int nkt = kend >> 6;
    for (int kt = 0; kt < nkt; kt++) {
        const int k0 = kt << 6;
        {
            const int r = tid >> 2, cq = tid & 3;
            const float* kp = K + ((size_t)b*sk + k0 + r)*cD + h*cDK + cq*16;
            float4 v0 = *(const float4*)(kp),     v1 = *(const float4*)(kp + 4);
            float4 v2 = *(const float4*)(kp + 8), v3 = *(const float4*)(kp + 12);
            *(uint4*)&Ks2[r*36 + cq*8] = make_uint4(
                h2u(__floats2half2_rn(v0.x, v0.y)), h2u(__floats2half2_rn(v0.z, v0.w)),
                h2u(__floats2half2_rn(v1.x, v1.y)), h2u(__floats2half2_rn(v1.z, v1.w)));
            *(uint4*)&Ks2[r*36 + cq*8 + 4] = make_uint4(
                h2u(__floats2half2_rn(v2.x, v2.y)), h2u(__floats2half2_rn(v2.z, v2.w)),
                h2u(__floats2half2_rn(v3.x, v3.y)), h2u(__floats2half2_rn(v3.z, v3.w)));
        }
        __syncthreads();

        float acc[2][2][4] = {};
#pragma unroll
        for (int kk2 = 0; kk2 < 32; kk2 += 8) {
            uint32_t af[2][4];
#pragma unroll
            for (int mt = 0; mt < 2; mt++) {
                int r0 = wm*32 + mt*16 + g;
                af[mt][0] = *(const uint32_t*)&Qs2[r0*36 + kk2 + tig];
                af[mt][1] = *(const uint32_t*)&Qs2[(r0 + 8)*36 + kk2 + tig];
                af[mt][2] = *(const uint32_t*)&Qs2[r0*36 + kk2 + 4 + tig];
                af[mt][3] = *(const uint32_t*)&Qs2[(r0 + 8)*36 + kk2 + 4 + tig];
            }
            uint32_t bf[2][2];
#pragma unroll
            for (int nt = 0; nt < 2; nt++) {
                int n = wn*16 + nt*8 + g;
                bf[nt][0] = *(const uint32_t*)&Ks2[n*36 + kk2 + tig];
                bf[nt][1] = *(const uint32_t*)&Ks2[n*36 + kk2 + 4 + tig];
            }
#pragma unroll
            for (int mt = 0; mt < 2; mt++)
#pragma unroll
                for (int nt = 0; nt < 2; nt++)
                    mma_f16(acc[mt][nt], af[mt][0], af[mt][1], af[mt][2], af[mt][3],
                            bf[nt][0], bf[nt][1]);
        }

#pragma unroll
        for (int mt = 0; mt < 2; mt++) {
#pragma unroll
            for (int nt = 0; nt < 2; nt++) {
                int qr = wm*32 + mt*16 + g;
                int kl = wn*16 + nt*8 + 2*tig;
                int kg = k0 + kl;
                bool m0 = (!CAUSAL) && msk[kg] == 0;
                bool m1 = (!CAUSAL) && msk[kg + 1] == 0;
#pragma unroll
                for (int rr = 0; rr < 2; rr++) {
                    int q = q0 + qr + rr*8;
                    float v0 = acc[mt][nt][rr*2 + 0] * scale;
                    float v1 = acc[mt][nt][rr*2 + 1] * scale;
                    if ((CAUSAL && kg     > q) || m0) v0 = -INFINITY;
                    if ((CAUSAL && kg + 1 > q) || m1) v1 = -INFINITY;
                    Ssm[(qr + rr*8)*SSTR + (kg >> 1)] = __floats2half2_rn(v0, v1);
                }
            }
        }
        __syncthreads();
    }

    // ---- softmax over smem S: 4 lanes per row, no pow2 assumptions ----
    const int kext2 = kend >> 1;
    {
        const int row = tid >> 2, qg = tid & 3;
        float m = -INFINITY;
        for (int i = qg; i < kext2; i += 4) {
            float2 f = __half22float2(Ssm[row*SSTR + i]);
            m = fmaxf(m, fmaxf(f.x, f.y));
        }
        m = fmaxf(m, __shfl_xor_sync(0xffffffffu, m, 1));
        m = fmaxf(m, __shfl_xor_sync(0xffffffffu, m, 2));

        float s = 0.f;
        for (int i = qg; i < kext2; i += 4) {
            float2 f = __half22float2(Ssm[row*SSTR + i]);
            float e0 = __expf(f.x - m), e1 = __expf(f.y - m);
            s += e0 + e1;
            Ssm[row*SSTR + i] = __floats2half2_rn(e0, e1);
        }
        s += __shfl_xor_sync(0xffffffffu, s, 1);
        s += __shfl_xor_sync(0xffffffffu, s, 2);
        const float inv = 1.0f / s;

        for (int i = qg; i < kext2; i += 4) {
            float2 f = __half22float2(Ssm[row*SSTR + i]);
            f.x *= inv; f.y *= inv;
            Ssm[row*SSTR + i] = __floats2half2_rn(f.x, f.y);
            if (WRITE_P)
                *(float2*)&P[((size_t)bh*cSQ + q0 + row)*sk + 2*i] = f;
        }
    }
    __syncthreads();

    // ---- A@V phase: stream V k32-tiles; P frags from smem ----
    float acc[2][2][4] = {};
    const int nvt = kend >> 5;
    for (int t = 0; t < nvt; t++) {
        const int k0 = t << 5;
        {
            const int k2l = tid >> 4, vd = (tid & 15) << 2;
            const float* vp0 = V + ((size_t)b*sk + k0 + 2*k2l)*cD + h*cDK + vd;
            const float* vp1 = vp0 + cD;
            float4 w0 = *(const float4*)vp0;
            float4 w1 = *(const float4*)vp1;
            *(uint4*)&Vs2[k2l*72 + vd] = make_uint4(
                h2u(__floats2half2_rn(w0.x, w1.x)), h2u(__floats2half2_rn(w0.y, w1.y)),
                h2u(__floats2half2_rn(w0.z, w1.z)), h2u(__floats2half2_rn(w0.w, w1.w)));
        }
        __syncthreads();

        const int kb = k0 >> 1;
#pragma unroll
        for (int c = 0; c < 2; c++) {
            uint32_t af[2][4];
#pragma unroll
            for (int mt = 0; mt < 2; mt++) {
                int r0 = wm*32 + mt*16 + g;
                af[mt][0] = *(const uint32_t*)&Ssm[r0*SSTR + kb + 8*c + tig];
                af[mt][1] = *(const uint32_t*)&Ssm[(r0 + 8)*SSTR + kb + 8*c + tig];
                af[mt][2] = *(const uint32_t*)&Ssm[r0*SSTR + kb + 8*c + 4 + tig];
                af[mt][3] = *(const uint32_t*)&Ssm[(r0 + 8)*SSTR + kb + 8*c + 4 + tig];
            }
            uint32_t bf[2][2];
#pragma unroll
            for (int nt = 0; nt < 2; nt++) {
                int n = wn*16 + nt*8 + g;
                bf[nt][0] = *(const uint32_t*)&Vs2[(8*c + tig)*72 + n];
                bf[nt][1] = *(const uint32_t*)&Vs2[(8*c + 4 + tig)*72 + n];
            }
#pragma unroll
            for (int mt = 0; mt < 2; mt++)
#pragma unroll
                for (int nt = 0; nt < 2; nt++)
                    mma_f16(acc[mt][nt], af[mt][0], af[mt][1], af[mt][2], af[mt][3],
                            bf[nt][0], bf[nt][1]);
        }
        __syncthreads();
    }

#pragma unroll
    for (int mt = 0; mt < 2; mt++) {
#pragma unroll
        for (int nt = 0; nt < 2; nt++) {
            int qr = wm*32 + mt*16 + g;
            int d  = wn*16 + nt*8 + 2*tig;
#pragma unroll
            for (int rr = 0; rr < 2; rr++) {
                size_t row = (size_t)b*cSQ + q0 + qr + rr*8;
                float2 v = { acc[mt][nt][rr*2 + 0], acc[mt][nt][rr*2 + 1] };
                *(float2*)&O[row*cD + h*cDK + d] = v;
            }
        }
    }
}

// smem sizes matching the template constants
constexpr int SMEM_SELF  = 64*260*4 + 64*36*4 + 64*36*4 + 16*72*4;           // 89600
constexpr int SMEM_CROSS = 64*516*4 + 64*36*4 + 64*36*4 + 16*72*4 + 4096;    // 159232

// ---------------------------------------------------------------------------
// out = LayerNorm(X + R) * g + b over last dim (D=1024). One block per row.
// ---------------------------------------------------------------------------
__global__ __launch_bounds__(256) void ln_residual_kernel(
    const float* __restrict__ X, const float* __restrict__ R,
    const float* __restrict__ g, const float* __restrict__ be,
    float* __restrict__ out)
{
    __shared__ float red[256];
    const size_t row = blockIdx.x;
    const int t = threadIdx.x;
    const float* xr = X + row*cD;
    const float* rr = R + row*cD;

    float v[4]; float s = 0.f;
#pragma unroll
    for (int i = 0; i < 4; i++) { v[i] = xr[t + i*256] + rr[t + i*256]; s += v[i]; }
    red[t] = s; __syncthreads();
    for (int k = 128; k > 0; k >>= 1) { if (t < k) red[t] += red[t+k]; __syncthreads(); }
    float mu = red[0] * (1.0f / cD); __syncthreads();

    float vs = 0.f;
#pragma unroll
    for (int i = 0; i < 4; i++) { float d = v[i] - mu; vs += d*d; }
    red[t] = vs; __syncthreads();
    for (int k = 128; k > 0; k >>= 1) { if (t < k) red[t] += red[t+k]; __syncthreads(); }
    float inv = rsqrtf(red[0] * (1.0f / cD) + 1e-5f);

    float* orow = out + row*cD;
#pragma unroll
    for (int i = 0; i < 4; i++) {
        int c = t + i*256;
        orow[c] = (v[i] - mu) * inv * g[c] + be[c];
    }
}

// ---------------------------------------------------------------------------
// Launch
// ---------------------------------------------------------------------------
extern "C" void kernel_launch(void* const* d_in, const int* in_sizes, int n_in,
                              void* d_out, int out_size)
{
    const float* x        = (const float*)d_in[0];
    const float* enc_o    = (const float*)d_in[1];
    const int*   enc_mask = (const int*)  d_in[2];
    const float* a1_wq = (const float*)d_in[3];
    const float* a1_bq = (const float*)d_in[4];
    const float* a1_wk = (const float*)d_in[5];
    const float* a1_bk = (const float*)d_in[6];
    const float* a1_wv = (const float*)d_in[7];
    const float* a1_bv = (const float*)d_in[8];
    const float* a1_wo = (const float*)d_in[9];
    const float* a1_bo = (const float*)d_in[10];
    const float* a2_wq = (const float*)d_in[11];
    const float* a2_bq = (const float*)d_in[12];
    const float* a2_wk = (const float*)d_in[13];
    const float* a2_bk = (const float*)d_in[14];
    const float* a2_wv = (const float*)d_in[15];
    const float* a2_bv = (const float*)d_in[16];
    const float* a2_wo = (const float*)d_in[17];
    const float* a2_bo = (const float*)d_in[18];
    const float* ff_w1 = (const float*)d_in[19];
    const float* ff_b1 = (const float*)d_in[20];
    const float* ff_w2 = (const float*)d_in[21];
    const float* ff_b2 = (const float*)d_in[22];
    const float* ln1_g = (const float*)d_in[23];
    const float* ln1_b = (const float*)d_in[24];
    const float* ln2_g = (const float*)d_in[25];
    const float* ln2_b = (const float*)d_in[26];
    const float* ln3_g = (const float*)d_in[27];
    const float* ln3_b = (const float*)d_in[28];

    float* out_x    = (float*)d_out;
    float* out_attn = out_x + (size_t)cB*cSQ*cD;

    float *bufQ, *bufK, *bufV, *bufC, *bufO, *bufX1, *bufX2, *bufF;
    cudaGetSymbolAddress((void**)&bufQ,  g_bufQ);
    cudaGetSymbolAddress((void**)&bufK,  g_bufK);
    cudaGetSymbolAddress((void**)&bufV,  g_bufV);
    cudaGetSymbolAddress((void**)&bufC,  g_bufC);
    cudaGetSymbolAddress((void**)&bufO,  g_bufO);
    cudaGetSymbolAddress((void**)&bufX1, g_bufX1);
    cudaGetSymbolAddress((void**)&bufX2, g_bufX2);
    cudaGetSymbolAddress((void**)&bufF,  g_bufF);

    cudaFuncSetAttribute(fused_attn_kernel<true, false>,
                         cudaFuncAttributeMaxDynamicSharedMemorySize, SMEM_SELF);
    cudaFuncSetAttribute(fused_attn_kernel<false, true>,
                         cudaFuncAttributeMaxDynamicSharedMemorySize, SMEM_CROSS);

    const float scale = 0.125f;   // 1/sqrt(64)
    const dim3 blk(256);
    const int M1 = cB * cSQ;      // 4096
    const int M2 = cB * cSK;      // 8192

    // ---- self-attention (causal, fused) ----
    gemm_fp16<false><<<dim3(cD/128, M1/128), blk>>>(x, a1_wq, a1_bq, bufQ, M1, cD, cD);
    gemm_fp16<false><<<dim3(cD/128, M1/128), blk>>>(x, a1_wk, a1_bk, bufK, M1, cD, cD);
    gemm_fp16<false><<<dim3(cD/128, M1/128), blk>>>(x, a1_wv, a1_bv, bufV, M1, cD, cD);
    fused_attn_kernel<true, false><<<dim3(cSQ/64, cB*cH), blk, SMEM_SELF>>>(
        bufQ, bufK, bufV, nullptr, nullptr, bufC, cSQ, scale);
    gemm_fp16<false><<<dim3(cD/128, M1/128), blk>>>(bufC, a1_wo, a1_bo, bufO, M1, cD, cD);
    ln_residual_kernel<<<M1, blk>>>(x, bufO, ln1_g, ln1_b, bufX1);

    // ---- cross-attention (kv mask, fused; P streamed to d_out) ----
    gemm_fp16<false><<<dim3(cD/128, M1/128), blk>>>(bufX1, a2_wq, a2_bq, bufQ, M1, cD, cD);
    gemm_fp16<false><<<dim3(cD/128, M2/128), blk>>>(enc_o, a2_wk, a2_bk, bufK, M2, cD, cD);
    gemm_fp16<false><<<dim3(cD/128, M2/128), blk>>>(enc_o, a2_wv, a2_bv, bufV, M2, cD, cD);
    fused_attn_kernel<false, true><<<dim3(cSQ/64, cB*cH), blk, SMEM_CROSS>>>(
        bufQ, bufK, bufV, enc_mask, out_attn, bufC, cSK, scale);
    gemm_fp16<false><<<dim3(cD/128, M1/128), blk>>>(bufC, a2_wo, a2_bo, bufO, M1, cD, cD);
    ln_residual_kernel<<<M1, blk>>>(bufX1, bufO, ln2_g, ln2_b, bufX2);

    // ---- feed-forward ----
    gemm_fp16<true ><<<dim3(cF/128, M1/128), blk>>>(bufX2, ff_w1, ff_b1, bufF, M1, cF, cD);
    gemm_fp16<false><<<dim3(cD/128, M1/128), blk>>>(bufF, ff_w2, ff_b2, bufO, M1, cD, cF);
    ln_residual_kernel<<<M1, blk>>>(bufX2, bufO, ln3_g, ln3_b, out_x);
}

// round 11
// speedup vs baseline: 1.0483x; 1.0205x over previous
#include <cuda_runtime.h>
#include <cuda_fp16.h>
#include <math.h>
#include <stdint.h>

// Problem constants
constexpr int cB  = 8;
constexpr int cSQ = 512;
constexpr int cSK = 1024;
constexpr int cD  = 1024;
constexpr int cH  = 16;
constexpr int cDK = 64;
constexpr int cF  = 4096;

// ---------------------------------------------------------------------------
// Scratch (device globals; no allocations allowed)
// ---------------------------------------------------------------------------
__device__ float g_bufQ [(size_t)cB*cSQ*cD];
__device__ float g_bufK [(size_t)cB*cSK*cD];
__device__ float g_bufV [(size_t)cB*cSK*cD];
__device__ float g_bufC [(size_t)cB*cSQ*cD];
__device__ float g_bufO [(size_t)cB*cSQ*cD];
__device__ float g_bufX1[(size_t)cB*cSQ*cD];
__device__ float g_bufX2[(size_t)cB*cSQ*cD];
__device__ float g_bufF [(size_t)cB*cSQ*cF];

// ---------------------------------------------------------------------------
// helpers
// ---------------------------------------------------------------------------
__device__ __forceinline__ void mma_f16(float c[4],
    uint32_t a0, uint32_t a1, uint32_t a2, uint32_t a3,
    uint32_t b0, uint32_t b1)
{
    asm volatile(
        "mma.sync.aligned.m16n8k16.row.col.f32.f16.f16.f32 "
        "{%0,%1,%2,%3}, {%4,%5,%6,%7}, {%8,%9}, {%0,%1,%2,%3};"
        : "+f"(c[0]), "+f"(c[1]), "+f"(c[2]), "+f"(c[3])
        : "r"(a0), "r"(a1), "r"(a2), "r"(a3), "r"(b0), "r"(b1));
}

__device__ __forceinline__ uint32_t h2u(__half2 h) {
    return *reinterpret_cast<uint32_t*>(&h);
}

// ---------------------------------------------------------------------------
// fp16 GEMM (round-6 proven): C[M,N] = A[M,K] @ W[K,N] + bias (+ReLU).
// 128x128 block, 256 threads / 8 warps (2x4), warp tile 64x32, k-step 16.
// ---------------------------------------------------------------------------
template<bool RELU>
__global__ __launch_bounds__(256, 2) void gemm_fp16(
    const float* __restrict__ A, const float* __restrict__ W,
    const float* __restrict__ bias, float* __restrict__ C,
    int M, int N, int K)
{
    __shared__ __half2 As2[128 * 12];
    __shared__ __half2 Bs2[8 * 136];

    const int tid  = threadIdx.x;
    const int bx   = blockIdx.x, by = blockIdx.y;
    const int warp = tid >> 5, lane = tid & 31;
    const int g = lane >> 2, tig = lane & 3;
    const int wm = warp >> 2;
    const int wn = warp & 3;

    const int ar  = tid >> 1;
    const int ac2 = (tid & 1) * 4;
    const float* Asrc = A + (size_t)(by*128 + ar)*K + ac2*2;

    const int bk2 = warp;
    const int bn  = lane * 4;
    const float* Bsrc0 = W + (size_t)(2*bk2    )*N + bx*128 + bn;
    const float* Bsrc1 = W + (size_t)(2*bk2 + 1)*N + bx*128 + bn;

    const int nk = K >> 4;
    float acc[4][4][4] = {};

    float4 pa0 = *(const float4*)(Asrc);
    float4 pa1 = *(const float4*)(Asrc + 4);
    float4 pb0 = *(const float4*)(Bsrc0);
    float4 pb1 = *(const float4*)(Bsrc1);

    for (int kt = 0; kt < nk; kt++) {
        {
            __half2 a0 = __floats2half2_rn(pa0.x, pa0.y);
            __half2 a1 = __floats2half2_rn(pa0.z, pa0.w);
            __half2 a2 = __floats2half2_rn(pa1.x, pa1.y);
            __half2 a3 = __floats2half2_rn(pa1.z, pa1.w);
            *(uint4*)&As2[ar*12 + ac2] = make_uint4(h2u(a0), h2u(a1), h2u(a2), h2u(a3));

            __half2 b0 = __floats2half2_rn(pb0.x, pb1.x);
            __half2 b1 = __floats2half2_rn(pb0.y, pb1.y);
            __half2 b2 = __floats2half2_rn(pb0.z, pb1.z);
            __half2 b3 = __floats2half2_rn(pb0.w, pb1.w);
            *(uint4*)&Bs2[bk2*136 + bn] = make_uint4(h2u(b0), h2u(b1), h2u(b2), h2u(b3));
        }
        __syncthreads();

        if (kt + 1 < nk) {
            const int kn = (kt + 1) << 4;
            pa0 = *(const float4*)(Asrc + kn);
            pa1 = *(const float4*)(Asrc + kn + 4);
            pb0 = *(const float4*)(Bsrc0 + (size_t)kn*N);
            pb1 = *(const float4*)(Bsrc1 + (size_t)kn*N);
        }

        uint32_t af[4][4];
#pragma unroll
        for (int mt = 0; mt < 4; mt++) {
            int r0 = wm*64 + mt*16 + g;
            af[mt][0] = *(uint32_t*)&As2[r0*12 + tig];
            af[mt][1] = *(uint32_t*)&As2[(r0 + 8)*12 + tig];
            af[mt][2] = *(uint32_t*)&As2[r0*12 + 4 + tig];
            af[mt][3] = *(uint32_t*)&As2[(r0 + 8)*12 + 4 + tig];
        }
        uint32_t bf[4][2];
#pragma unroll
        for (int nt = 0; nt < 4; nt++) {
            int n = wn*32 + nt*8 + g;
            bf[nt][0] = *(uint32_t*)&Bs2[tig*136 + n];
            bf[nt][1] = *(uint32_t*)&Bs2[(4 + tig)*136 + n];
        }
#pragma unroll
        for (int mt = 0; mt < 4; mt++)
#pragma unroll
            for (int nt = 0; nt < 4; nt++)
                mma_f16(acc[mt][nt], af[mt][0], af[mt][1], af[mt][2], af[mt][3],
                        bf[nt][0], bf[nt][1]);
        __syncthreads();
    }

#pragma unroll
    for (int mt = 0; mt < 4; mt++) {
#pragma unroll
        for (int nt = 0; nt < 4; nt++) {
            int row0 = by*128 + wm*64 + mt*16 + g;
            int col  = bx*128 + wn*32 + nt*8 + 2*tig;
            float b0 = bias[col], b1 = bias[col + 1];
            float2 v0 = { acc[mt][nt][0] + b0, acc[mt][nt][1] + b1 };
            float2 v1 = { acc[mt][nt][2] + b0, acc[mt][nt][3] + b1 };
            if (RELU) {
                v0.x = fmaxf(v0.x, 0.f); v0.y = fmaxf(v0.y, 0.f);
                v1.x = fmaxf(v1.x, 0.f); v1.y = fmaxf(v1.y, 0.f);
            }
            *(float2*)&C[(size_t)row0*N + col]       = v0;
            *(float2*)&C[(size_t)(row0 + 8)*N + col] = v1;
        }
    }
}

// ---------------------------------------------------------------------------
// Fused attention v2: 32 q-rows per block for occupancy.
// qk^T -> softmax -> (optional coalesced P writeout) -> @V, S fp16 in smem.
// CAUSAL: kend rounded up to 64 (extra cols masked -inf -> exp 0).
// Warp layout: 8 warps 2x4; wm in {0,1} -> 16 q-rows each; wn -> 16 cols.
// ---------------------------------------------------------------------------
template<bool CAUSAL, bool WRITE_P>
__global__ __launch_bounds__(256) void fused_attn32_kernel(
    const float* __restrict__ Q, const float* __restrict__ K,
    const float* __restrict__ V, const int* __restrict__ kvmask,
    float* __restrict__ P, float* __restrict__ O, int sk, float scale)
{
    constexpr int SSTR = CAUSAL ? 260 : 516;    // half2 stride, ==4 mod 32
    constexpr int OFF_S   = 0;
    constexpr int OFF_Q   = OFF_S + 32*SSTR*4;
    constexpr int OFF_K   = OFF_Q + 32*36*4;
    constexpr int OFF_V   = OFF_K + 64*36*4;
    constexpr int OFF_MSK = OFF_V + 16*72*4;
    constexpr int OFF_INV = OFF_MSK + (CAUSAL ? 0 : 4096);

    extern __shared__ char smraw[];
    __half2* Ssm    = (__half2*)(smraw + OFF_S);
    __half2* Qs2    = (__half2*)(smraw + OFF_Q);
    __half2* Ks2    = (__half2*)(smraw + OFF_K);
    __half2* Vs2    = (__half2*)(smraw + OFF_V);
    int*     msk    = (int*)    (smraw + OFF_MSK);
    float*   rowInv = (float*)  (smraw + OFF_INV);

    const int bh = blockIdx.y;
    const int b  = bh >> 4, h = bh & 15;
    const int q0 = blockIdx.x * 32;
    const int tid  = threadIdx.x;
    const int warp = tid >> 5, lane = tid & 31;
    const int g = lane >> 2, tig = lane & 3;
    const int wm = warp >> 2;     // 0..1 -> 16 q-rows
    const int wn = warp & 3;      // 0..3 -> 16 cols

    // causal: round k-extent up to the 64-wide K-tile (extra cols masked)
    const int kend = CAUSAL ? (((q0 + 32 + 63) >> 6) << 6) : sk;

    // ---- load Q tile (32 x 64) as half2 [row][d2] stride 36 ----
    {
        const int r = tid >> 3, cq = tid & 7;
        const float* qp = Q + ((size_t)b*cSQ + q0 + r)*cD + h*cDK + cq*8;
        float4 v0 = *(const float4*)(qp), v1 = *(const float4*)(qp + 4);
        *(uint4*)&Qs2[r*36 + cq*4] = make_uint4(
            h2u(__floats2half2_rn(v0.x, v0.y)), h2u(__floats2half2_rn(v0.z, v0.w)),
            h2u(__floats2half2_rn(v1.x, v1.y)), h2u(__floats2half2_rn(v1.z, v1.w)));
    }
    if (!CAUSAL)
        for (int i = tid; i < sk; i += 256) msk[i] = kvmask[b*sk + i];

    // ---- QK^T phase: stream 64-row K tiles, S -> smem fp16 ----
    const int nkt = kend >> 6;
    for (int kt = 0; kt < nkt; kt++) {
        const int k0 = kt << 6;
        {
            const int r = tid >> 2, cq = tid & 3;
            const float* kp = K + ((size_t)b*sk + k0 + r)*cD + h*cDK + cq*16;
            float4 v0 = *(const float4*)(kp),     v1 = *(const float4*)(kp + 4);
            float4 v2 = *(const float4*)(kp + 8), v3 = *(const float4*)(kp + 12);
            *(uint4*)&Ks2[r*36 + cq*8] = make_uint4(
                h2u(__floats2half2_rn(v0.x, v0.y)), h2u(__floats2half2_rn(v0.z, v0.w)),
                h2u(__floats2half2_rn(v1.x, v1.y)), h2u(__floats2half2_rn(v1.z, v1.w)));
            *(uint4*)&Ks2[r*36 + cq*8 + 4] = make_uint4(
                h2u(__floats2half2_rn(v2.x, v2.y)), h2u(__floats2half2_rn(v2.z, v2.w)),
                h2u(__floats2half2_rn(v3.x, v3.y)), h2u(__floats2half2_rn(v3.z, v3.w)));
        }
        __syncthreads();

        float acc[2][4] = {};
#pragma unroll
        for (int kk2 = 0; kk2 < 32; kk2 += 8) {
            uint32_t af[4];
            {
                int r0 = wm*16 + g;
                af[0] = *(const uint32_t*)&Qs2[r0*36 + kk2 + tig];
                af[1] = *(const uint32_t*)&Qs2[(r0 + 8)*36 + kk2 + tig];
                af[2] = *(const uint32_t*)&Qs2[r0*36 + kk2 + 4 + tig];
                af[3] = *(const uint32_t*)&Qs2[(r0 + 8)*36 + kk2 + 4 + tig];
            }
            uint32_t bf[2][2];
#pragma unroll
            for (int nt = 0; nt < 2; nt++) {
                int n = wn*16 + nt*8 + g;
                bf[nt][0] = *(const uint32_t*)&Ks2[n*36 + kk2 + tig];
                bf[nt][1] = *(const uint32_t*)&Ks2[n*36 + kk2 + 4 + tig];
            }
#pragma unroll
            for (int nt = 0; nt < 2; nt++)
                mma_f16(acc[nt], af[0], af[1], af[2], af[3], bf[nt][0], bf[nt][1]);
        }

#pragma unroll
        for (int nt = 0; nt < 2; nt++) {
            int qr = wm*16 + g;
            int kl = wn*16 + nt*8 + 2*tig;
            int kg = k0 + kl;
            bool m0 = (!CAUSAL) && msk[kg] == 0;
            bool m1 = (!CAUSAL) && msk[kg + 1] == 0;
#pragma unroll
            for (int rr = 0; rr < 2; rr++) {
                int q = q0 + qr + rr*8;
                float v0 = acc[nt][rr*2 + 0] * scale;
                float v1 = acc[nt][rr*2 + 1] * scale;
                if ((CAUSAL && kg     > q) || m0) v0 = -INFINITY;
                if ((CAUSAL && kg + 1 > q) || m1) v1 = -INFINITY;
                Ssm[(qr + rr*8)*SSTR + (kg >> 1)] = __floats2half2_rn(v0, v1);
            }
        }
        __syncthreads();
    }

    // ---- softmax: 8 lanes per row (32 rows x 8 = 256 threads) ----
    const int kext2 = kend >> 1;
    {
        const int row = tid >> 3, l8 = tid & 7;
        float m = -INFINITY;
        for (int i = l8; i < kext2; i += 8) {
            float2 f = __half22float2(Ssm[row*SSTR + i]);
            m = fmaxf(m, fmaxf(f.x, f.y));
        }
        m = fmaxf(m, __shfl_xor_sync(0xffffffffu, m, 1));
        m = fmaxf(m, __shfl_xor_sync(0xffffffffu, m, 2));
        m = fmaxf(m, __shfl_xor_sync(0xffffffffu, m, 4));

        float s = 0.f;
        for (int i = l8; i < kext2; i += 8) {
            float2 f = __half22float2(Ssm[row*SSTR + i]);
            float e0 = __expf(f.x - m), e1 = __expf(f.y - m);
            s += e0 + e1;
            Ssm[row*SSTR + i] = __floats2half2_rn(e0, e1);
        }
        s += __shfl_xor_sync(0xffffffffu, s, 1);
        s += __shfl_xor_sync(0xffffffffu, s, 2);
        s += __shfl_xor_sync(0xffffffffu, s, 4);
        if (l8 == 0) rowInv[row] = 1.0f / s;
    }
    __syncthreads();

    // ---- normalize, warp-per-row (fully coalesced P writeout) ----
#pragma unroll
    for (int r = warp; r < 32; r += 8) {
        const float inv = rowInv[r];
        float* Prow = WRITE_P ? &P[((size_t)bh*cSQ + q0 + r)*sk] : nullptr;
        for (int i = lane; i < kext2; i += 32) {
            float2 f = __half22float2(Ssm[r*SSTR + i]);
            f.x *= inv; f.y *= inv;
            Ssm[r*SSTR + i] = __floats2half2_rn(f.x, f.y);
            if (WRITE_P) *(float2*)&Prow[2*i] = f;
        }
    }
    __syncthreads();

    // ---- A@V phase: stream V k32-tiles; P frags from smem ----
    float acc[2][4] = {};
    const int nvt = kend >> 5;
    for (int t = 0; t < nvt; t++) {
        const int k0 = t << 5;
        {
            const int k2l = tid >> 4, vd = (tid & 15) << 2;
            const float* vp0 = V + ((size_t)b*sk + k0 + 2*k2l)*cD + h*cDK + vd;
            const float* vp1 = vp0 + cD;
            float4 w0 = *(const float4*)vp0;
            float4 w1 = *(const float4*)vp1;
            *(uint4*)&Vs2[k2l*72 + vd] = make_uint4(
                h2u(__floats2half2_rn(w0.x, w1.x)), h2u(__floats2half2_rn(w0.y, w1.y)),
                h2u(__floats2half2_rn(w0.z, w1.z)), h2u(__floats2half2_rn(w0.w, w1.w)));
        }
        __syncthreads();

        const int kb = k0 >> 1;
#pragma unroll
        for (int c = 0; c < 2; c++) {
            uint32_t af[4];
            {
                int r0 = wm*16 + g;
                af[0] = *(const uint32_t*)&Ssm[r0*SSTR + kb + 8*c + tig];
                af[1] = *(const uint32_t*)&Ssm[(r0 + 8)*SSTR + kb + 8*c + tig];
                af[2] = *(const uint32_t*)&Ssm[r0*SSTR + kb + 8*c + 4 + tig];
                af[3] = *(const uint32_t*)&Ssm[(r0 + 8)*SSTR + kb + 8*c + 4 + tig];
            }
            uint32_t bf[2][2];
#pragma unroll
            for (int nt = 0; nt < 2; nt++) {
                int n = wn*16 + nt*8 + g;
                bf[nt][0] = *(const uint32_t*)&Vs2[(8*c + tig)*72 + n];
                bf[nt][1] = *(const uint32_t*)&Vs2[(8*c + 4 + tig)*72 + n];
            }
#pragma unroll
            for (int nt = 0; nt < 2; nt++)
                mma_f16(acc[nt], af[0], af[1], af[2], af[3], bf[nt][0], bf[nt][1]);
        }
        __syncthreads();
    }

#pragma unroll
    for (int nt = 0; nt < 2; nt++) {
        int qr = wm*16 + g;
        int d  = wn*16 + nt*8 + 2*tig;
#pragma unroll
        for (int rr = 0; rr < 2; rr++) {
            size_t row = (size_t)b*cSQ + q0 + qr + rr*8;
            float2 v = { acc[nt][rr*2 + 0], acc[nt][rr*2 + 1] };
            *(float2*)&O[row*cD + h*cDK + d] = v;
        }
    }
}

// smem sizes matching the template constants
constexpr int SMEM_SELF32  = 32*260*4 + 32*36*4 + 64*36*4 + 16*72*4 + 128;          // 51840
constexpr int SMEM_CROSS32 = 32*516*4 + 32*36*4 + 64*36*4 + 16*72*4 + 4096 + 128;   // 88704

// ---------------------------------------------------------------------------
// out = LayerNorm(X + R) * g + b over last dim (D=1024). One block per row.
// ---------------------------------------------------------------------------
__global__ __launch_bounds__(256) void ln_residual_kernel(
    const float* __restrict__ X, const float* __restrict__ R,
    const float* __restrict__ g, const float* __restrict__ be,
    float* __restrict__ out)
{
    __shared__ float red[256];
    const size_t row = blockIdx.x;
    const int t = threadIdx.x;
    const float* xr = X + row*cD;
    const float* rr = R + row*cD;

    float v[4]; float s = 0.f;
#pragma unroll
    for (int i = 0; i < 4; i++) { v[i] = xr[t + i*256] + rr[t + i*256]; s += v[i]; }
    red[t] = s; __syncthreads();
    for (int k = 128; k > 0; k >>= 1) { if (t < k) red[t] += red[t+k]; __syncthreads(); }
    float mu = red[0] * (1.0f / cD); __syncthreads();

    float vs = 0.f;
#pragma unroll
    for (int i = 0; i < 4; i++) { float d = v[i] - mu; vs += d*d; }
    red[t] = vs; __syncthreads();
    for (int k = 128; k > 0; k >>= 1) { if (t < k) red[t] += red[t+k]; __syncthreads(); }
    float inv = rsqrtf(red[0] * (1.0f / cD) + 1e-5f);

    float* orow = out + row*cD;
#pragma unroll
    for (int i = 0; i < 4; i++) {
        int c = t + i*256;
        orow[c] = (v[i] - mu) * inv * g[c] + be[c];
    }
}

// ---------------------------------------------------------------------------
// Launch
// ---------------------------------------------------------------------------
extern "C" void kernel_launch(void* const* d_in, const int* in_sizes, int n_in,
                              void* d_out, int out_size)
{
    const float* x        = (const float*)d_in[0];
    const float* enc_o    = (const float*)d_in[1];
    const int*   enc_mask = (const int*)  d_in[2];
    const float* a1_wq = (const float*)d_in[3];
    const float* a1_bq = (const float*)d_in[4];
    const float* a1_wk = (const float*)d_in[5];
    const float* a1_bk = (const float*)d_in[6];
    const float* a1_wv = (const float*)d_in[7];
    const float* a1_bv = (const float*)d_in[8];
    const float* a1_wo = (const float*)d_in[9];
    const float* a1_bo = (const float*)d_in[10];
    const float* a2_wq = (const float*)d_in[11];
    const float* a2_bq = (const float*)d_in[12];
    const float* a2_wk = (const float*)d_in[13];
    const float* a2_bk = (const float*)d_in[14];
    const float* a2_wv = (const float*)d_in[15];
    const float* a2_bv = (const float*)d_in[16];
    const float* a2_wo = (const float*)d_in[17];
    const float* a2_bo = (const float*)d_in[18];
    const float* ff_w1 = (const float*)d_in[19];
    const float* ff_b1 = (const float*)d_in[20];
    const float* ff_w2 = (const float*)d_in[21];
    const float* ff_b2 = (const float*)d_in[22];
    const float* ln1_g = (const float*)d_in[23];
    const float* ln1_b = (const float*)d_in[24];
    const float* ln2_g = (const float*)d_in[25];
    const float* ln2_b = (const float*)d_in[26];
    const float* ln3_g = (const float*)d_in[27];
    const float* ln3_b = (const float*)d_in[28];

    float* out_x    = (float*)d_out;
    float* out_attn = out_x + (size_t)cB*cSQ*cD;

    float *bufQ, *bufK, *bufV, *bufC, *bufO, *bufX1, *bufX2, *bufF;
    cudaGetSymbolAddress((void**)&bufQ,  g_bufQ);
    cudaGetSymbolAddress((void**)&bufK,  g_bufK);
    cudaGetSymbolAddress((void**)&bufV,  g_bufV);
    cudaGetSymbolAddress((void**)&bufC,  g_bufC);
    cudaGetSymbolAddress((void**)&bufO,  g_bufO);
    cudaGetSymbolAddress((void**)&bufX1, g_bufX1);
    cudaGetSymbolAddress((void**)&bufX2, g_bufX2);
    cudaGetSymbolAddress((void**)&bufF,  g_bufF);

    cudaFuncSetAttribute(fused_attn32_kernel<true, false>,
                         cudaFuncAttributeMaxDynamicSharedMemorySize, SMEM_SELF32);
    cudaFuncSetAttribute(fused_attn32_kernel<false, true>,
                         cudaFuncAttributeMaxDynamicSharedMemorySize, SMEM_CROSS32);

    const float scale = 0.125f;   // 1/sqrt(64)
    const dim3 blk(256);
    const int M1 = cB * cSQ;      // 4096
    const int M2 = cB * cSK;      // 8192

    // ---- self-attention (causal, fused) ----
    gemm_fp16<false><<<dim3(cD/128, M1/128), blk>>>(x, a1_wq, a1_bq, bufQ, M1, cD, cD);
    gemm_fp16<false><<<dim3(cD/128, M1/128), blk>>>(x, a1_wk, a1_bk, bufK, M1, cD, cD);
    gemm_fp16<false><<<dim3(cD/128, M1/128), blk>>>(x, a1_wv, a1_bv, bufV, M1, cD, cD);
    fused_attn32_kernel<true, false><<<dim3(cSQ/32, cB*cH), blk, SMEM_SELF32>>>(
        bufQ, bufK, bufV, nullptr, nullptr, bufC, cSQ, scale);
    gemm_fp16<false><<<dim3(cD/128, M1/128), blk>>>(bufC, a1_wo, a1_bo, bufO, M1, cD, cD);
    ln_residual_kernel<<<M1, blk>>>(x, bufO, ln1_g, ln1_b, bufX1);

    // ---- cross-attention (kv mask, fused; P streamed to d_out) ----
    gemm_fp16<false><<<dim3(cD/128, M1/128), blk>>>(bufX1, a2_wq, a2_bq, bufQ, M1, cD, cD);
    gemm_fp16<false><<<dim3(cD/128, M2/128), blk>>>(enc_o, a2_wk, a2_bk, bufK, M2, cD, cD);
    gemm_fp16<false><<<dim3(cD/128, M2/128), blk>>>(enc_o, a2_wv, a2_bv, bufV, M2, cD, cD);
    fused_attn32_kernel<false, true><<<dim3(cSQ/32, cB*cH), blk, SMEM_CROSS32>>>(
        bufQ, bufK, bufV, enc_mask, out_attn, bufC, cSK, scale);
    gemm_fp16<false><<<dim3(cD/128, M1/128), blk>>>(bufC, a2_wo, a2_bo, bufO, M1, cD, cD);
    ln_residual_kernel<<<M1, blk>>>(bufX1, bufO, ln2_g, ln2_b, bufX2);

    // ---- feed-forward ----
    gemm_fp16<true ><<<dim3(cF/128, M1/128), blk>>>(bufX2, ff_w1, ff_b1, bufF, M1, cF, cD);
    gemm_fp16<false><<<dim3(cD/128, M1/128), blk>>>(bufF, ff_w2, ff_b2, bufO, M1, cD, cF);
    ln_residual_kernel<<<M1, blk>>>(bufX2, bufO, ln3_g, ln3_b, out_x);
}

// round 12
// speedup vs baseline: 1.1413x; 1.0887x over previous
#include <cuda_runtime.h>
#include <cuda_fp16.h>
#include <math.h>
#include <stdint.h>

// Problem constants
constexpr int cB  = 8;
constexpr int cSQ = 512;
constexpr int cSK = 1024;
constexpr int cD  = 1024;
constexpr int cH  = 16;
constexpr int cDK = 64;
constexpr int cF  = 4096;

// ---------------------------------------------------------------------------
// Scratch (device globals; no allocations allowed)
// ---------------------------------------------------------------------------
__device__ float g_bufQ [(size_t)cB*cSQ*cD];
__device__ float g_bufK [(size_t)cB*cSK*cD];
__device__ float g_bufV [(size_t)cB*cSK*cD];
__device__ float g_bufC [(size_t)cB*cSQ*cD];
__device__ float g_bufO [(size_t)cB*cSQ*cD];
__device__ float g_bufX1[(size_t)cB*cSQ*cD];
__device__ float g_bufX2[(size_t)cB*cSQ*cD];
__device__ float g_bufF [(size_t)cB*cSQ*cF];

// ---------------------------------------------------------------------------
// helpers
// ---------------------------------------------------------------------------
__device__ __forceinline__ void mma_f16(float c[4],
    uint32_t a0, uint32_t a1, uint32_t a2, uint32_t a3,
    uint32_t b0, uint32_t b1)
{
    asm volatile(
        "mma.sync.aligned.m16n8k16.row.col.f32.f16.f16.f32 "
        "{%0,%1,%2,%3}, {%4,%5,%6,%7}, {%8,%9}, {%0,%1,%2,%3};"
        : "+f"(c[0]), "+f"(c[1]), "+f"(c[2]), "+f"(c[3])
        : "r"(a0), "r"(a1), "r"(a2), "r"(a3), "r"(b0), "r"(b1));
}

__device__ __forceinline__ uint32_t h2u(__half2 h) {
    return *reinterpret_cast<uint32_t*>(&h);
}

__device__ __forceinline__ uint4 pack8(float4 a, float4 b) {
    return make_uint4(
        h2u(__floats2half2_rn(a.x, a.y)), h2u(__floats2half2_rn(a.z, a.w)),
        h2u(__floats2half2_rn(b.x, b.y)), h2u(__floats2half2_rn(b.z, b.w)));
}

// ---------------------------------------------------------------------------
// fp16 GEMM (round-6 proven): C[M,N] = A[M,K] @ W[K,N] + bias (+ReLU).
// ---------------------------------------------------------------------------
template<bool RELU>
__global__ __launch_bounds__(256, 2) void gemm_fp16(
    const float* __restrict__ A, const float* __restrict__ W,
    const float* __restrict__ bias, float* __restrict__ C,
    int M, int N, int K)
{
    __shared__ __half2 As2[128 * 12];
    __shared__ __half2 Bs2[8 * 136];

    const int tid  = threadIdx.x;
    const int bx   = blockIdx.x, by = blockIdx.y;
    const int warp = tid >> 5, lane = tid & 31;
    const int g = lane >> 2, tig = lane & 3;
    const int wm = warp >> 2;
    const int wn = warp & 3;

    const int ar  = tid >> 1;
    const int ac2 = (tid & 1) * 4;
    const float* Asrc = A + (size_t)(by*128 + ar)*K + ac2*2;

    const int bk2 = warp;
    const int bn  = lane * 4;
    const float* Bsrc0 = W + (size_t)(2*bk2    )*N + bx*128 + bn;
    const float* Bsrc1 = W + (size_t)(2*bk2 + 1)*N + bx*128 + bn;

    const int nk = K >> 4;
    float acc[4][4][4] = {};

    float4 pa0 = *(const float4*)(Asrc);
    float4 pa1 = *(const float4*)(Asrc + 4);
    float4 pb0 = *(const float4*)(Bsrc0);
    float4 pb1 = *(const float4*)(Bsrc1);

    for (int kt = 0; kt < nk; kt++) {
        {
            *(uint4*)&As2[ar*12 + ac2] = pack8(pa0, pa1);
            __half2 b0 = __floats2half2_rn(pb0.x, pb1.x);
            __half2 b1 = __floats2half2_rn(pb0.y, pb1.y);
            __half2 b2 = __floats2half2_rn(pb0.z, pb1.z);
            __half2 b3 = __floats2half2_rn(pb0.w, pb1.w);
            *(uint4*)&Bs2[bk2*136 + bn] = make_uint4(h2u(b0), h2u(b1), h2u(b2), h2u(b3));
        }
        __syncthreads();

        if (kt + 1 < nk) {
            const int kn = (kt + 1) << 4;
            pa0 = *(const float4*)(Asrc + kn);
            pa1 = *(const float4*)(Asrc + kn + 4);
            pb0 = *(const float4*)(Bsrc0 + (size_t)kn*N);
            pb1 = *(const float4*)(Bsrc1 + (size_t)kn*N);
        }

        uint32_t af[4][4];
#pragma unroll
        for (int mt = 0; mt < 4; mt++) {
            int r0 = wm*64 + mt*16 + g;
            af[mt][0] = *(uint32_t*)&As2[r0*12 + tig];
            af[mt][1] = *(uint32_t*)&As2[(r0 + 8)*12 + tig];
            af[mt][2] = *(uint32_t*)&As2[r0*12 + 4 + tig];
            af[mt][3] = *(uint32_t*)&As2[(r0 + 8)*12 + 4 + tig];
        }
        uint32_t bf[4][2];
#pragma unroll
        for (int nt = 0; nt < 4; nt++) {
            int n = wn*32 + nt*8 + g;
            bf[nt][0] = *(uint32_t*)&Bs2[tig*136 + n];
            bf[nt][1] = *(uint32_t*)&Bs2[(4 + tig)*136 + n];
        }
#pragma unroll
        for (int mt = 0; mt < 4; mt++)
#pragma unroll
            for (int nt = 0; nt < 4; nt++)
                mma_f16(acc[mt][nt], af[mt][0], af[mt][1], af[mt][2], af[mt][3],
                        bf[nt][0], bf[nt][1]);
        __syncthreads();
    }

#pragma unroll
    for (int mt = 0; mt < 4; mt++) {
#pragma unroll
        for (int nt = 0; nt < 4; nt++) {
            int row0 = by*128 + wm*64 + mt*16 + g;
            int col  = bx*128 + wn*32 + nt*8 + 2*tig;
            float b0 = bias[col], b1 = bias[col + 1];
            float2 v0 = { acc[mt][nt][0] + b0, acc[mt][nt][1] + b1 };
            float2 v1 = { acc[mt][nt][2] + b0, acc[mt][nt][3] + b1 };
            if (RELU) {
                v0.x = fmaxf(v0.x, 0.f); v0.y = fmaxf(v0.y, 0.f);
                v1.x = fmaxf(v1.x, 0.f); v1.y = fmaxf(v1.y, 0.f);
            }
            *(float2*)&C[(size_t)row0*N + col]       = v0;
            *(float2*)&C[(size_t)(row0 + 8)*N + col] = v1;
        }
    }
}

// ---------------------------------------------------------------------------
// Fused SELF attention (causal): 64 q-rows/block, K/V register prefetch.
// ---------------------------------------------------------------------------
__global__ __launch_bounds__(256) void attn_self_fused(
    const float* __restrict__ Q, const float* __restrict__ K,
    const float* __restrict__ V, float* __restrict__ O, float scale)
{
    constexpr int SSTR = 260;
    extern __shared__ char smraw[];
    __half2* Ssm = (__half2*)(smraw);
    __half2* Qs2 = (__half2*)(smraw + 64*SSTR*4);
    __half2* Ks2 = (__half2*)(smraw + 64*SSTR*4 + 64*36*4);
    __half2* Vs2 = (__half2*)(smraw + 64*SSTR*4 + 2*64*36*4);

    const int bh = blockIdx.y;
    const int b  = bh >> 4, h = bh & 15;
    const int q0 = blockIdx.x * 64;
    const int tid  = threadIdx.x;
    const int warp = tid >> 5, lane = tid & 31;
    const int g = lane >> 2, tig = lane & 3;
    const int wm = warp >> 2;     // 0..1 -> 32 q
    const int wn = warp & 3;      // 0..3 -> 16 cols

    const int kend = q0 + 64;
    const int r4 = tid >> 2, c4 = tid & 3;

    const float* Kbase = K + ((size_t)b*cSQ)*cD + h*cDK;
    const float* Vbase = V + ((size_t)b*cSQ)*cD + h*cDK;

    // K prefetch registers + helpers
    float4 pk0, pk1, pk2, pk3;
    auto ldgK = [&](int kt) {
        const float* kp = Kbase + (size_t)(kt*64 + r4)*cD + c4*16;
        pk0 = *(const float4*)(kp);     pk1 = *(const float4*)(kp + 4);
        pk2 = *(const float4*)(kp + 8); pk3 = *(const float4*)(kp + 12);
    };
    auto stsK = [&]() {
        *(uint4*)&Ks2[r4*36 + c4*8]     = pack8(pk0, pk1);
        *(uint4*)&Ks2[r4*36 + c4*8 + 4] = pack8(pk2, pk3);
    };

    ldgK(0);

    // Q tile (64 x 64) -> smem
    {
        const float* qp = Q + ((size_t)b*cSQ + q0 + r4)*cD + h*cDK + c4*16;
        float4 v0 = *(const float4*)(qp),     v1 = *(const float4*)(qp + 4);
        float4 v2 = *(const float4*)(qp + 8), v3 = *(const float4*)(qp + 12);
        *(uint4*)&Qs2[r4*36 + c4*8]     = pack8(v0, v1);
        *(uint4*)&Qs2[r4*36 + c4*8 + 4] = pack8(v2, v3);
    }

    // ---- QK^T phase ----
    const int nkt = kend >> 6;
    for (int kt = 0; kt < nkt; kt++) {
        stsK();
        __syncthreads();
        if (kt + 1 < nkt) ldgK(kt + 1);    // overlap with mma

        const int k0 = kt << 6;
        float acc[2][2][4] = {};
#pragma unroll
        for (int kk2 = 0; kk2 < 32; kk2 += 8) {
            uint32_t af[2][4];
#pragma unroll
            for (int mt = 0; mt < 2; mt++) {
                int r0 = wm*32 + mt*16 + g;
                af[mt][0] = *(const uint32_t*)&Qs2[r0*36 + kk2 + tig];
                af[mt][1] = *(const uint32_t*)&Qs2[(r0 + 8)*36 + kk2 + tig];
                af[mt][2] = *(const uint32_t*)&Qs2[r0*36 + kk2 + 4 + tig];
                af[mt][3] = *(const uint32_t*)&Qs2[(r0 + 8)*36 + kk2 + 4 + tig];
            }
            uint32_t bf[2][2];
#pragma unroll
            for (int nt = 0; nt < 2; nt++) {
                int n = wn*16 + nt*8 + g;
                bf[nt][0] = *(const uint32_t*)&Ks2[n*36 + kk2 + tig];
                bf[nt][1] = *(const uint32_t*)&Ks2[n*36 + kk2 + 4 + tig];
            }
#pragma unroll
            for (int mt = 0; mt < 2; mt++)
#pragma unroll
                for (int nt = 0; nt < 2; nt++)
                    mma_f16(acc[mt][nt], af[mt][0], af[mt][1], af[mt][2], af[mt][3],
                            bf[nt][0], bf[nt][1]);
        }

#pragma unroll
        for (int mt = 0; mt < 2; mt++) {
#pragma unroll
            for (int nt = 0; nt < 2; nt++) {
                int qr = wm*32 + mt*16 + g;
                int kg = k0 + wn*16 + nt*8 + 2*tig;
#pragma unroll
                for (int rr = 0; rr < 2; rr++) {
                    int q = q0 + qr + rr*8;
                    float v0 = acc[mt][nt][rr*2 + 0] * scale;
                    float v1 = acc[mt][nt][rr*2 + 1] * scale;
                    if (kg     > q) v0 = -INFINITY;
                    if (kg + 1 > q) v1 = -INFINITY;
                    Ssm[(qr + rr*8)*SSTR + (kg >> 1)] = __floats2half2_rn(v0, v1);
                }
            }
        }
        __syncthreads();
    }

    // V prefetch registers + helpers
    const int vk2 = tid >> 4, vd = (tid & 15) << 2;
    float4 pv0, pv1;
    auto ldgV = [&](int t) {
        const float* vp = Vbase + (size_t)(t*32 + 2*vk2)*cD + vd;
        pv0 = *(const float4*)vp;
        pv1 = *(const float4*)(vp + cD);
    };
    auto stsV = [&]() {
        *(uint4*)&Vs2[vk2*72 + vd] = make_uint4(
            h2u(__floats2half2_rn(pv0.x, pv1.x)), h2u(__floats2half2_rn(pv0.y, pv1.y)),
            h2u(__floats2half2_rn(pv0.z, pv1.z)), h2u(__floats2half2_rn(pv0.w, pv1.w)));
    };

    ldgV(0);   // overlaps with softmax

    // ---- softmax: 4 lanes per row ----
    const int kext2 = kend >> 1;
    {
        const int row = tid >> 2, qg = tid & 3;
        float m = -INFINITY;
        for (int i = qg; i < kext2; i += 4) {
            float2 f = __half22float2(Ssm[row*SSTR + i]);
            m = fmaxf(m, fmaxf(f.x, f.y));
        }
        m = fmaxf(m, __shfl_xor_sync(0xffffffffu, m, 1));
        m = fmaxf(m, __shfl_xor_sync(0xffffffffu, m, 2));

        float s = 0.f;
        for (int i = qg; i < kext2; i += 4) {
            float2 f = __half22float2(Ssm[row*SSTR + i]);
            float e0 = __expf(f.x - m), e1 = __expf(f.y - m);
            s += e0 + e1;
            Ssm[row*SSTR + i] = __floats2half2_rn(e0, e1);
        }
        s += __shfl_xor_sync(0xffffffffu, s, 1);
        s += __shfl_xor_sync(0xffffffffu, s, 2);
        const float inv = 1.0f / s;

        for (int i = qg; i < kext2; i += 4) {
            float2 f = __half22float2(Ssm[row*SSTR + i]);
            Ssm[row*SSTR + i] = __floats2half2_rn(f.x * inv, f.y * inv);
        }
    }
    __syncthreads();

    // ---- A@V phase ----
    float acc[2][2][4] = {};
    const int nvt = kend >> 5;
    for (int t = 0; t < nvt; t++) {
        stsV();
        __syncthreads();
        if (t + 1 < nvt) ldgV(t + 1);

        const int kb = t << 4;
#pragma unroll
        for (int c = 0; c < 2; c++) {
            uint32_t af[2][4];
#pragma unroll
            for (int mt = 0; mt < 2; mt++) {
                int r0 = wm*32 + mt*16 + g;
                af[mt][0] = *(const uint32_t*)&Ssm[r0*SSTR + kb + 8*c + tig];
                af[mt][1] = *(const uint32_t*)&Ssm[(r0 + 8)*SSTR + kb + 8*c + tig];
                af[mt][2] = *(const uint32_t*)&Ssm[r0*SSTR + kb + 8*c + 4 + tig];
                af[mt][3] = *(const uint32_t*)&Ssm[(r0 + 8)*SSTR + kb + 8*c + 4 + tig];
            }
            uint32_t bf[2][2];
#pragma unroll
            for (int nt = 0; nt < 2; nt++) {
                int n = wn*16 + nt*8 + g;
                bf[nt][0] = *(const uint32_t*)&Vs2[(8*c + tig)*72 + n];
                bf[nt][1] = *(const uint32_t*)&Vs2[(8*c + 4 + tig)*72 + n];
            }
#pragma unroll
            for (int mt = 0; mt < 2; mt++)
#pragma unroll
                for (int nt = 0; nt < 2; nt++)
                    mma_f16(acc[mt][nt], af[mt][0], af[mt][1], af[mt][2], af[mt][3],
                            bf[nt][0], bf[nt][1]);
        }
        __syncthreads();
    }

#pragma unroll
    for (int mt = 0; mt < 2; mt++) {
#pragma unroll
        for (int nt = 0; nt < 2; nt++) {
            int qr = wm*32 + mt*16 + g;
            int d  = wn*16 + nt*8 + 2*tig;
#pragma unroll
            for (int rr = 0; rr < 2; rr++) {
                size_t row = (size_t)b*cSQ + q0 + qr + rr*8;
                float2 v = { acc[mt][nt][rr*2 + 0], acc[mt][nt][rr*2 + 1] };
                *(float2*)&O[row*cD + h*cDK + d] = v;
            }
        }
    }
}
constexpr int SMEM_SELF = 64*260*4 + 2*(64*36*4) + 16*72*4;   // 89600

// ---------------------------------------------------------------------------
// Fused CROSS attention: 32 q-rows/block, kv-mask, coalesced P writeout,
// K/V register prefetch.
// ---------------------------------------------------------------------------
__global__ __launch_bounds__(256) void attn_cross_fused(
    const float* __restrict__ Q, const float* __restrict__ K,
    const float* __restrict__ V, const int* __restrict__ kvmask,
    float* __restrict__ P, float* __restrict__ O, float scale)
{
    constexpr int SSTR = 516;
    constexpr int SK = cSK;
    extern __shared__ char smraw[];
    __half2* Ssm    = (__half2*)(smraw);
    __half2* Qs2    = (__half2*)(smraw + 32*SSTR*4);
    __half2* Ks2    = (__half2*)(smraw + 32*SSTR*4 + 32*36*4);
    __half2* Vs2    = (__half2*)(smraw + 32*SSTR*4 + 32*36*4 + 64*36*4);
    int*     msk    = (int*)    (smraw + 32*SSTR*4 + 32*36*4 + 64*36*4 + 16*72*4);
    float*   rowInv = (float*)  (smraw + 32*SSTR*4 + 32*36*4 + 64*36*4 + 16*72*4 + 4096);

    const int bh = blockIdx.y;
    const int b  = bh >> 4, h = bh & 15;
    const int q0 = blockIdx.x * 32;
    const int tid  = threadIdx.x;
    const int warp = tid >> 5, lane = tid & 31;
    const int g = lane >> 2, tig = lane & 3;
    const int wm = warp >> 2;     // 0..1 -> 16 q-rows
    const int wn = warp & 3;      // 0..3 -> 16 cols

    const int r4 = tid >> 2, c4 = tid & 3;
    const float* Kbase = K + ((size_t)b*SK)*cD + h*cDK;
    const float* Vbase = V + ((size_t)b*SK)*cD + h*cDK;

    float4 pk0, pk1, pk2, pk3;
    auto ldgK = [&](int kt) {
        const float* kp = Kbase + (size_t)(kt*64 + r4)*cD + c4*16;
        pk0 = *(const float4*)(kp);     pk1 = *(const float4*)(kp + 4);
        pk2 = *(const float4*)(kp + 8); pk3 = *(const float4*)(kp + 12);
    };
    auto stsK = [&]() {
        *(uint4*)&Ks2[r4*36 + c4*8]     = pack8(pk0, pk1);
        *(uint4*)&Ks2[r4*36 + c4*8 + 4] = pack8(pk2, pk3);
    };

    ldgK(0);

    // Q tile (32 x 64)
    {
        const int r = tid >> 3, cq = tid & 7;
        const float* qp = Q + ((size_t)b*cSQ + q0 + r)*cD + h*cDK + cq*8;
        float4 v0 = *(const float4*)(qp), v1 = *(const float4*)(qp + 4);
        *(uint4*)&Qs2[r*36 + cq*4] = pack8(v0, v1);
    }
    for (int i = tid; i < SK; i += 256) msk[i] = kvmask[b*SK + i];

    // ---- QK^T phase ----
    const int nkt = SK >> 6;
    for (int kt = 0; kt < nkt; kt++) {
        stsK();
        __syncthreads();
        if (kt + 1 < nkt) ldgK(kt + 1);

        const int k0 = kt << 6;
        float acc[2][4] = {};
#pragma unroll
        for (int kk2 = 0; kk2 < 32; kk2 += 8) {
            uint32_t af[4];
            {
                int r0 = wm*16 + g;
                af[0] = *(const uint32_t*)&Qs2[r0*36 + kk2 + tig];
                af[1] = *(const uint32_t*)&Qs2[(r0 + 8)*36 + kk2 + tig];
                af[2] = *(const uint32_t*)&Qs2[r0*36 + kk2 + 4 + tig];
                af[3] = *(const uint32_t*)&Qs2[(r0 + 8)*36 + kk2 + 4 + tig];
            }
            uint32_t bf[2][2];
#pragma unroll
            for (int nt = 0; nt < 2; nt++) {
                int n = wn*16 + nt*8 + g;
                bf[nt][0] = *(const uint32_t*)&Ks2[n*36 + kk2 + tig];
                bf[nt][1] = *(const uint32_t*)&Ks2[n*36 + kk2 + 4 + tig];
            }
#pragma unroll
            for (int nt = 0; nt < 2; nt++)
                mma_f16(acc[nt], af[0], af[1], af[2], af[3], bf[nt][0], bf[nt][1]);
        }

#pragma unroll
        for (int nt = 0; nt < 2; nt++) {
            int qr = wm*16 + g;
            int kg = k0 + wn*16 + nt*8 + 2*tig;
            bool m0 = msk[kg] == 0;
            bool m1 = msk[kg + 1] == 0;
#pragma unroll
            for (int rr = 0; rr < 2; rr++) {
                float v0 = m0 ? -INFINITY : acc[nt][rr*2 + 0] * scale;
                float v1 = m1 ? -INFINITY : acc[nt][rr*2 + 1] * scale;
                Ssm[(qr + rr*8)*SSTR + (kg >> 1)] = __floats2half2_rn(v0, v1);
            }
        }
        __syncthreads();
    }

    const int vk2 = tid >> 4, vd = (tid & 15) << 2;
    float4 pv0, pv1;
    auto ldgV = [&](int t) {
        const float* vp = Vbase + (size_t)(t*32 + 2*vk2)*cD + vd;
        pv0 = *(const float4*)vp;
        pv1 = *(const float4*)(vp + cD);
    };
    auto stsV = [&]() {
        *(uint4*)&Vs2[vk2*72 + vd] = make_uint4(
            h2u(__floats2half2_rn(pv0.x, pv1.x)), h2u(__floats2half2_rn(pv0.y, pv1.y)),
            h2u(__floats2half2_rn(pv0.z, pv1.z)), h2u(__floats2half2_rn(pv0.w, pv1.w)));
    };

    ldgV(0);   // overlaps with softmax

    // ---- softmax: 8 lanes per row ----
    constexpr int kext2 = SK >> 1;
    {
        const int row = tid >> 3, l8 = tid & 7;
        float m = -INFINITY;
        for (int i = l8; i < kext2; i += 8) {
            float2 f = __half22float2(Ssm[row*SSTR + i]);
            m = fmaxf(m, fmaxf(f.x, f.y));
        }
        m = fmaxf(m, __shfl_xor_sync(0xffffffffu, m, 1));
        m = fmaxf(m, __shfl_xor_sync(0xffffffffu, m, 2));
        m = fmaxf(m, __shfl_xor_sync(0xffffffffu, m, 4));

        float s = 0.f;
        for (int i = l8; i < kext2; i += 8) {
            float2 f = __half22float2(Ssm[row*SSTR + i]);
            float e0 = __expf(f.x - m), e1 = __expf(f.y - m);
            s += e0 + e1;
            Ssm[row*SSTR + i] = __floats2half2_rn(e0, e1);
        }
        s += __shfl_xor_sync(0xffffffffu, s, 1);
        s += __shfl_xor_sync(0xffffffffu, s, 2);
        s += __shfl_xor_sync(0xffffffffu, s, 4);
        if (l8 == 0) rowInv[row] = 1.0f / s;
    }
    __syncthreads();

    // ---- normalize + coalesced P writeout (warp per row) ----
#pragma unroll
    for (int r = warp; r < 32; r += 8) {
        const float inv = rowInv[r];
        float* Prow = &P[((size_t)bh*cSQ + q0 + r)*SK];
        for (int i = lane; i < kext2; i += 32) {
            float2 f = __half22float2(Ssm[r*SSTR + i]);
            f.x *= inv; f.y *= inv;
            Ssm[r*SSTR + i] = __floats2half2_rn(f.x, f.y);
            *(float2*)&Prow[2*i] = f;
        }
    }
    __syncthreads();

    // ---- A@V phase ----
    float acc[2][4] = {};
    const int nvt = SK >> 5;
    for (int t = 0; t < nvt; t++) {
        stsV();
        __syncthreads();
        if (t + 1 < nvt) ldgV(t + 1);

        const int kb = t << 4;
#pragma unroll
        for (int c = 0; c < 2; c++) {
            uint32_t af[4];
            {
                int r0 = wm*16 + g;
                af[0] = *(const uint32_t*)&Ssm[r0*SSTR + kb + 8*c + tig];
                af[1] = *(const uint32_t*)&Ssm[(r0 + 8)*SSTR + kb + 8*c + tig];
                af[2] = *(const uint32_t*)&Ssm[r0*SSTR + kb + 8*c + 4 + tig];
                af[3] = *(const uint32_t*)&Ssm[(r0 + 8)*SSTR + kb + 8*c + 4 + tig];
            }
            uint32_t bf[2][2];
#pragma unroll
            for (int nt = 0; nt < 2; nt++) {
                int n = wn*16 + nt*8 + g;
                bf[nt][0] = *(const uint32_t*)&Vs2[(8*c + tig)*72 + n];
                bf[nt][1] = *(const uint32_t*)&Vs2[(8*c + 4 + tig)*72 + n];
            }
#pragma unroll
            for (int nt = 0; nt < 2; nt++)
                mma_f16(acc[nt], af[0], af[1], af[2], af[3], bf[nt][0], bf[nt][1]);
        }
        __syncthreads();
    }

#pragma unroll
    for (int nt = 0; nt < 2; nt++) {
        int qr = wm*16 + g;
        int d  = wn*16 + nt*8 + 2*tig;
#pragma unroll
        for (int rr = 0; rr < 2; rr++) {
            size_t row = (size_t)b*cSQ + q0 + qr + rr*8;
            float2 v = { acc[nt][rr*2 + 0], acc[nt][rr*2 + 1] };
            *(float2*)&O[row*cD + h*cDK + d] = v;
        }
    }
}
constexpr int SMEM_CROSS = 32*516*4 + 32*36*4 + 64*36*4 + 16*72*4 + 4096 + 128;  // 88704

// ---------------------------------------------------------------------------
// out = LayerNorm(X + R) * g + b, D=1024. Shuffle reductions, 2 syncs.
// ---------------------------------------------------------------------------
__global__ __launch_bounds__(256) void ln_residual_kernel(
    const float* __restrict__ X, const float* __restrict__ R,
    const float* __restrict__ g, const float* __restrict__ be,
    float* __restrict__ out)
{
    __shared__ float redm[8];
    __shared__ float redv[8];
    const size_t row = blockIdx.x;
    const int t = threadIdx.x;
    const int warp = t >> 5, lane = t & 31;
    const float* xr = X + row*cD;
    const float* rr = R + row*cD;

    float v[4]; float s = 0.f;
#pragma unroll
    for (int i = 0; i < 4; i++) { v[i] = xr[t + i*256] + rr[t + i*256]; s += v[i]; }
#pragma unroll
    for (int off = 16; off > 0; off >>= 1)
        s += __shfl_xor_sync(0xffffffffu, s, off);
    if (lane == 0) redm[warp] = s;
    __syncthreads();
    float mu = redm[0];
#pragma unroll
    for (int i = 1; i < 8; i++) mu += redm[i];
    mu *= (1.0f / cD);

    float vs = 0.f;
#pragma unroll
    for (int i = 0; i < 4; i++) { float d = v[i] - mu; vs += d*d; }
#pragma unroll
    for (int off = 16; off > 0; off >>= 1)
        vs += __shfl_xor_sync(0xffffffffu, vs, off);
    if (lane == 0) redv[warp] = vs;
    __syncthreads();
    float var = redv[0];
#pragma unroll
    for (int i = 1; i < 8; i++) var += redv[i];
    float inv = rsqrtf(var * (1.0f / cD) + 1e-5f);

    float* orow = out + row*cD;
#pragma unroll
    for (int i = 0; i < 4; i++) {
        int c = t + i*256;
        orow[c] = (v[i] - mu) * inv * g[c] + be[c];
    }
}

// ---------------------------------------------------------------------------
// Launch
// ---------------------------------------------------------------------------
extern "C" void kernel_launch(void* const* d_in, const int* in_sizes, int n_in,
                              void* d_out, int out_size)
{
    const float* x        = (const float*)d_in[0];
    const float* enc_o    = (const float*)d_in[1];
    const int*   enc_mask = (const int*)  d_in[2];
    const float* a1_wq = (const float*)d_in[3];
    const float* a1_bq = (const float*)d_in[4];
    const float* a1_wk = (const float*)d_in[5];
    const float* a1_bk = (const float*)d_in[6];
    const float* a1_wv = (const float*)d_in[7];
    const float* a1_bv = (const float*)d_in[8];
    const float* a1_wo = (const float*)d_in[9];
    const float* a1_bo = (const float*)d_in[10];
    const float* a2_wq = (const float*)d_in[11];
    const float* a2_bq = (const float*)d_in[12];
    const float* a2_wk = (const float*)d_in[13];
    const float* a2_bk = (const float*)d_in[14];
    const float* a2_wv = (const float*)d_in[15];
    const float* a2_bv = (const float*)d_in[16];
    const float* a2_wo = (const float*)d_in[17];
    const float* a2_bo = (const float*)d_in[18];
    const float* ff_w1 = (const float*)d_in[19];
    const float* ff_b1 = (const float*)d_in[20];
    const float* ff_w2 = (const float*)d_in[21];
    const float* ff_b2 = (const float*)d_in[22];
    const float* ln1_g = (const float*)d_in[23];
    const float* ln1_b = (const float*)d_in[24];
    const float* ln2_g = (const float*)d_in[25];
    const float* ln2_b = (const float*)d_in[26];
    const float* ln3_g = (const float*)d_in[27];
    const float* ln3_b = (const float*)d_in[28];

    float* out_x    = (float*)d_out;
    float* out_attn = out_x + (size_t)cB*cSQ*cD;

    float *bufQ, *bufK, *bufV, *bufC, *bufO, *bufX1, *bufX2, *bufF;
    cudaGetSymbolAddress((void**)&bufQ,  g_bufQ);
    cudaGetSymbolAddress((void**)&bufK,  g_bufK);
    cudaGetSymbolAddress((void**)&bufV,  g_bufV);
    cudaGetSymbolAddress((void**)&bufC,  g_bufC);
    cudaGetSymbolAddress((void**)&bufO,  g_bufO);
    cudaGetSymbolAddress((void**)&bufX1, g_bufX1);
    cudaGetSymbolAddress((void**)&bufX2, g_bufX2);
    cudaGetSymbolAddress((void**)&bufF,  g_bufF);

    cudaFuncSetAttribute(attn_self_fused,
                         cudaFuncAttributeMaxDynamicSharedMemorySize, SMEM_SELF);
    cudaFuncSetAttribute(attn_cross_fused,
                         cudaFuncAttributeMaxDynamicSharedMemorySize, SMEM_CROSS);

    const float scale = 0.125f;   // 1/sqrt(64)
    const dim3 blk(256);
    const int M1 = cB * cSQ;      // 4096
    const int M2 = cB * cSK;      // 8192

    // ---- self-attention (causal, fused) ----
    gemm_fp16<false><<<dim3(cD/128, M1/128), blk>>>(x, a1_wq, a1_bq, bufQ, M1, cD, cD);
    gemm_fp16<false><<<dim3(cD/128, M1/128), blk>>>(x, a1_wk, a1_bk, bufK, M1, cD, cD);
    gemm_fp16<false><<<dim3(cD/128, M1/128), blk>>>(x, a1_wv, a1_bv, bufV, M1, cD, cD);
    attn_self_fused<<<dim3(cSQ/64, cB*cH), blk, SMEM_SELF>>>(
        bufQ, bufK, bufV, bufC, scale);
    gemm_fp16<false><<<dim3(cD/128, M1/128), blk>>>(bufC, a1_wo, a1_bo, bufO, M1, cD, cD);
    ln_residual_kernel<<<M1, blk>>>(x, bufO, ln1_g, ln1_b, bufX1);

    // ---- cross-attention (kv mask, fused; P streamed to d_out) ----
    gemm_fp16<false><<<dim3(cD/128, M1/128), blk>>>(bufX1, a2_wq, a2_bq, bufQ, M1, cD, cD);
    gemm_fp16<false><<<dim3(cD/128, M2/128), blk>>>(enc_o, a2_wk, a2_bk, bufK, M2, cD, cD);
    gemm_fp16<false><<<dim3(cD/128, M2/128), blk>>>(enc_o, a2_wv, a2_bv, bufV, M2, cD, cD);
    attn_cross_fused<<<dim3(cSQ/32, cB*cH), blk, SMEM_CROSS>>>(
        bufQ, bufK, bufV, enc_mask, out_attn, bufC, scale);
    gemm_fp16<false><<<dim3(cD/128, M1/128), blk>>>(bufC, a2_wo, a2_bo, bufO, M1, cD, cD);
    ln_residual_kernel<<<M1, blk>>>(bufX1, bufO, ln2_g, ln2_b, bufX2);

    // ---- feed-forward ----
    gemm_fp16<true ><<<dim3(cF/128, M1/128), blk>>>(bufX2, ff_w1, ff_b1, bufF, M1, cF, cD);
    gemm_fp16<false><<<dim3(cD/128, M1/128), blk>>>(bufF, ff_w2, ff_b2, bufO, M1, cD, cF);
    ln_residual_kernel<<<M1, blk>>>(bufX2, bufO, ln3_g, ln3_b, out_x);
}

// round 13
// speedup vs baseline: 1.1961x; 1.0481x over previous
#include <cuda_runtime.h>
#include <cuda_fp16.h>
#include <math.h>
#include <stdint.h>

// Problem constants
constexpr int cB  = 8;
constexpr int cSQ = 512;
constexpr int cSK = 1024;
constexpr int cD  = 1024;
constexpr int cH  = 16;
constexpr int cDK = 64;
constexpr int cF  = 4096;

// ---------------------------------------------------------------------------
// Scratch (device globals; no allocations allowed)
// ---------------------------------------------------------------------------
__device__ float g_bufQ [(size_t)cB*cSQ*cD];
__device__ float g_bufK [(size_t)cB*cSK*cD];
__device__ float g_bufV [(size_t)cB*cSK*cD];
__device__ float g_bufC [(size_t)cB*cSQ*cD];
__device__ float g_bufO [(size_t)cB*cSQ*cD];
__device__ float g_bufX1[(size_t)cB*cSQ*cD];
__device__ float g_bufX2[(size_t)cB*cSQ*cD];
__device__ float g_bufF [(size_t)cB*cSQ*cF];

// ---------------------------------------------------------------------------
// helpers
// ---------------------------------------------------------------------------
__device__ __forceinline__ void mma_f16(float c[4],
    uint32_t a0, uint32_t a1, uint32_t a2, uint32_t a3,
    uint32_t b0, uint32_t b1)
{
    asm volatile(
        "mma.sync.aligned.m16n8k16.row.col.f32.f16.f16.f32 "
        "{%0,%1,%2,%3}, {%4,%5,%6,%7}, {%8,%9}, {%0,%1,%2,%3};"
        : "+f"(c[0]), "+f"(c[1]), "+f"(c[2]), "+f"(c[3])
        : "r"(a0), "r"(a1), "r"(a2), "r"(a3), "r"(b0), "r"(b1));
}

__device__ __forceinline__ uint32_t h2u(__half2 h) {
    return *reinterpret_cast<uint32_t*>(&h);
}

__device__ __forceinline__ uint4 pack8(float4 a, float4 b) {
    return make_uint4(
        h2u(__floats2half2_rn(a.x, a.y)), h2u(__floats2half2_rn(a.z, a.w)),
        h2u(__floats2half2_rn(b.x, b.y)), h2u(__floats2half2_rn(b.z, b.w)));
}

// Pointer set for multi-output GEMM (blockIdx.z selects)
struct GemmSet {
    const float* W[3];
    const float* bias[3];
    float*       C[3];
};

// ---------------------------------------------------------------------------
// fp16 GEMM (round-6 proven body): C[M,N] = A[M,K] @ W[K,N] + bias (+ReLU).
// blockIdx.z selects (W, bias, C) from the set -> sibling GEMMs in 1 launch.
// ---------------------------------------------------------------------------
template<bool RELU>
__global__ __launch_bounds__(256, 2) void gemm_fp16(
    const float* __restrict__ A, GemmSet set,
    int M, int N, int K)
{
    const float* __restrict__ W    = set.W[blockIdx.z];
    const float* __restrict__ bias = set.bias[blockIdx.z];
    float* __restrict__       C    = set.C[blockIdx.z];

    __shared__ __half2 As2[128 * 12];
    __shared__ __half2 Bs2[8 * 136];

    const int tid  = threadIdx.x;
    const int bx   = blockIdx.x, by = blockIdx.y;
    const int warp = tid >> 5, lane = tid & 31;
    const int g = lane >> 2, tig = lane & 3;
    const int wm = warp >> 2;
    const int wn = warp & 3;

    const int ar  = tid >> 1;
    const int ac2 = (tid & 1) * 4;
    const float* Asrc = A + (size_t)(by*128 + ar)*K + ac2*2;

    const int bk2 = warp;
    const int bn  = lane * 4;
    const float* Bsrc0 = W + (size_t)(2*bk2    )*N + bx*128 + bn;
    const float* Bsrc1 = W + (size_t)(2*bk2 + 1)*N + bx*128 + bn;

    const int nk = K >> 4;
    float acc[4][4][4] = {};

    float4 pa0 = *(const float4*)(Asrc);
    float4 pa1 = *(const float4*)(Asrc + 4);
    float4 pb0 = *(const float4*)(Bsrc0);
    float4 pb1 = *(const float4*)(Bsrc1);

    for (int kt = 0; kt < nk; kt++) {
        {
            *(uint4*)&As2[ar*12 + ac2] = pack8(pa0, pa1);
            __half2 b0 = __floats2half2_rn(pb0.x, pb1.x);
            __half2 b1 = __floats2half2_rn(pb0.y, pb1.y);
            __half2 b2 = __floats2half2_rn(pb0.z, pb1.z);
            __half2 b3 = __floats2half2_rn(pb0.w, pb1.w);
            *(uint4*)&Bs2[bk2*136 + bn] = make_uint4(h2u(b0), h2u(b1), h2u(b2), h2u(b3));
        }
        __syncthreads();

        if (kt + 1 < nk) {
            const int kn = (kt + 1) << 4;
            pa0 = *(const float4*)(Asrc + kn);
            pa1 = *(const float4*)(Asrc + kn + 4);
            pb0 = *(const float4*)(Bsrc0 + (size_t)kn*N);
            pb1 = *(const float4*)(Bsrc1 + (size_t)kn*N);
        }

        uint32_t af[4][4];
#pragma unroll
        for (int mt = 0; mt < 4; mt++) {
            int r0 = wm*64 + mt*16 + g;
            af[mt][0] = *(uint32_t*)&As2[r0*12 + tig];
            af[mt][1] = *(uint32_t*)&As2[(r0 + 8)*12 + tig];
            af[mt][2] = *(uint32_t*)&As2[r0*12 + 4 + tig];
            af[mt][3] = *(uint32_t*)&As2[(r0 + 8)*12 + 4 + tig];
        }
        uint32_t bf[4][2];
#pragma unroll
        for (int nt = 0; nt < 4; nt++) {
            int n = wn*32 + nt*8 + g;
            bf[nt][0] = *(uint32_t*)&Bs2[tig*136 + n];
            bf[nt][1] = *(uint32_t*)&Bs2[(4 + tig)*136 + n];
        }
#pragma unroll
        for (int mt = 0; mt < 4; mt++)
#pragma unroll
            for (int nt = 0; nt < 4; nt++)
                mma_f16(acc[mt][nt], af[mt][0], af[mt][1], af[mt][2], af[mt][3],
                        bf[nt][0], bf[nt][1]);
        __syncthreads();
    }

#pragma unroll
    for (int mt = 0; mt < 4; mt++) {
#pragma unroll
        for (int nt = 0; nt < 4; nt++) {
            int row0 = by*128 + wm*64 + mt*16 + g;
            int col  = bx*128 + wn*32 + nt*8 + 2*tig;
            float b0 = bias[col], b1 = bias[col + 1];
            float2 v0 = { acc[mt][nt][0] + b0, acc[mt][nt][1] + b1 };
            float2 v1 = { acc[mt][nt][2] + b0, acc[mt][nt][3] + b1 };
            if (RELU) {
                v0.x = fmaxf(v0.x, 0.f); v0.y = fmaxf(v0.y, 0.f);
                v1.x = fmaxf(v1.x, 0.f); v1.y = fmaxf(v1.y, 0.f);
            }
            *(float2*)&C[(size_t)row0*N + col]       = v0;
            *(float2*)&C[(size_t)(row0 + 8)*N + col] = v1;
        }
    }
}

static inline GemmSet mkset(const float* w0, const float* b0, float* c0,
                            const float* w1 = nullptr, const float* b1 = nullptr, float* c1 = nullptr,
                            const float* w2 = nullptr, const float* b2 = nullptr, float* c2 = nullptr)
{
    GemmSet s;
    s.W[0] = w0; s.bias[0] = b0; s.C[0] = c0;
    s.W[1] = w1; s.bias[1] = b1; s.C[1] = c1;
    s.W[2] = w2; s.bias[2] = b2; s.C[2] = c2;
    return s;
}

// ---------------------------------------------------------------------------
// Fused SELF attention (causal): 64 q-rows/block, K/V register prefetch.
// Heavy tiles scheduled first (reversed q mapping).
// ---------------------------------------------------------------------------
__global__ __launch_bounds__(256) void attn_self_fused(
    const float* __restrict__ Q, const float* __restrict__ K,
    const float* __restrict__ V, float* __restrict__ O, float scale)
{
    constexpr int SSTR = 260;
    extern __shared__ char smraw[];
    __half2* Ssm = (__half2*)(smraw);
    __half2* Qs2 = (__half2*)(smraw + 64*SSTR*4);
    __half2* Ks2 = (__half2*)(smraw + 64*SSTR*4 + 64*36*4);
    __half2* Vs2 = (__half2*)(smraw + 64*SSTR*4 + 2*64*36*4);

    const int bh = blockIdx.y;
    const int b  = bh >> 4, h = bh & 15;
    const int q0 = (gridDim.x - 1 - blockIdx.x) * 64;   // heavy blocks first
    const int tid  = threadIdx.x;
    const int warp = tid >> 5, lane = tid & 31;
    const int g = lane >> 2, tig = lane & 3;
    const int wm = warp >> 2;     // 0..1 -> 32 q
    const int wn = warp & 3;      // 0..3 -> 16 cols

    const int kend = q0 + 64;
    const int r4 = tid >> 2, c4 = tid & 3;

    const float* Kbase = K + ((size_t)b*cSQ)*cD + h*cDK;
    const float* Vbase = V + ((size_t)b*cSQ)*cD + h*cDK;

    float4 pk0, pk1, pk2, pk3;
    auto ldgK = [&](int kt) {
        const float* kp = Kbase + (size_t)(kt*64 + r4)*cD + c4*16;
        pk0 = *(const float4*)(kp);     pk1 = *(const float4*)(kp + 4);
        pk2 = *(const float4*)(kp + 8); pk3 = *(const float4*)(kp + 12);
    };
    auto stsK = [&]() {
        *(uint4*)&Ks2[r4*36 + c4*8]     = pack8(pk0, pk1);
        *(uint4*)&Ks2[r4*36 + c4*8 + 4] = pack8(pk2, pk3);
    };

    ldgK(0);

    {
        const float* qp = Q + ((size_t)b*cSQ + q0 + r4)*cD + h*cDK + c4*16;
        float4 v0 = *(const float4*)(qp),     v1 = *(const float4*)(qp + 4);
        float4 v2 = *(const float4*)(qp + 8), v3 = *(const float4*)(qp + 12);
        *(uint4*)&Qs2[r4*36 + c4*8]     = pack8(v0, v1);
        *(uint4*)&Qs2[r4*36 + c4*8 + 4] = pack8(v2, v3);
    }

    // ---- QK^T phase ----
    const int nkt = kend >> 6;
    for (int kt = 0; kt < nkt; kt++) {
        stsK();
        __syncthreads();
        if (kt + 1 < nkt) ldgK(kt + 1);

        const int k0 = kt << 6;
        float acc[2][2][4] = {};
#pragma unroll
        for (int kk2 = 0; kk2 < 32; kk2 += 8) {
            uint32_t af[2][4];
#pragma unroll
            for (int mt = 0; mt < 2; mt++) {
                int r0 = wm*32 + mt*16 + g;
                af[mt][0] = *(const uint32_t*)&Qs2[r0*36 + kk2 + tig];
                af[mt][1] = *(const uint32_t*)&Qs2[(r0 + 8)*36 + kk2 + tig];
                af[mt][2] = *(const uint32_t*)&Qs2[r0*36 + kk2 + 4 + tig];
                af[mt][3] = *(const uint32_t*)&Qs2[(r0 + 8)*36 + kk2 + 4 + tig];
            }
            uint32_t bf[2][2];
#pragma unroll
            for (int nt = 0; nt < 2; nt++) {
                int n = wn*16 + nt*8 + g;
                bf[nt][0] = *(const uint32_t*)&Ks2[n*36 + kk2 + tig];
                bf[nt][1] = *(const uint32_t*)&Ks2[n*36 + kk2 + 4 + tig];
            }
#pragma unroll
            for (int mt = 0; mt < 2; mt++)
#pragma unroll
                for (int nt = 0; nt < 2; nt++)
                    mma_f16(acc[mt][nt], af[mt][0], af[mt][1], af[mt][2], af[mt][3],
                            bf[nt][0], bf[nt][1]);
        }

#pragma unroll
        for (int mt = 0; mt < 2; mt++) {
#pragma unroll
            for (int nt = 0; nt < 2; nt++) {
                int qr = wm*32 + mt*16 + g;
                int kg = k0 + wn*16 + nt*8 + 2*tig;
#pragma unroll
                for (int rr = 0; rr < 2; rr++) {
                    int q = q0 + qr + rr*8;
                    float v0 = acc[mt][nt][rr*2 + 0] * scale;
                    float v1 = acc[mt][nt][rr*2 + 1] * scale;
                    if (kg     > q) v0 = -INFINITY;
                    if (kg + 1 > q) v1 = -INFINITY;
                    Ssm[(qr + rr*8)*SSTR + (kg >> 1)] = __floats2half2_rn(v0, v1);
                }
            }
        }
        __syncthreads();
    }

    const int vk2 = tid >> 4, vd = (tid & 15) << 2;
    float4 pv0, pv1;
    auto ldgV = [&](int t) {
        const float* vp = Vbase + (size_t)(t*32 + 2*vk2)*cD + vd;
        pv0 = *(const float4*)vp;
        pv1 = *(const float4*)(vp + cD);
    };
    auto stsV = [&]() {
        *(uint4*)&Vs2[vk2*72 + vd] = make_uint4(
            h2u(__floats2half2_rn(pv0.x, pv1.x)), h2u(__floats2half2_rn(pv0.y, pv1.y)),
            h2u(__floats2half2_rn(pv0.z, pv1.z)), h2u(__floats2half2_rn(pv0.w, pv1.w)));
    };

    ldgV(0);

    // ---- softmax: 4 lanes per row ----
    const int kext2 = kend >> 1;
    {
        const int row = tid >> 2, qg = tid & 3;
        float m = -INFINITY;
        for (int i = qg; i < kext2; i += 4) {
            float2 f = __half22float2(Ssm[row*SSTR + i]);
            m = fmaxf(m, fmaxf(f.x, f.y));
        }
        m = fmaxf(m, __shfl_xor_sync(0xffffffffu, m, 1));
        m = fmaxf(m, __shfl_xor_sync(0xffffffffu, m, 2));

        float s = 0.f;
        for (int i = qg; i < kext2; i += 4) {
            float2 f = __half22float2(Ssm[row*SSTR + i]);
            float e0 = __expf(f.x - m), e1 = __expf(f.y - m);
            s += e0 + e1;
            Ssm[row*SSTR + i] = __floats2half2_rn(e0, e1);
        }
        s += __shfl_xor_sync(0xffffffffu, s, 1);
        s += __shfl_xor_sync(0xffffffffu, s, 2);
        const float inv = 1.0f / s;

        for (int i = qg; i < kext2; i += 4) {
            float2 f = __half22float2(Ssm[row*SSTR + i]);
            Ssm[row*SSTR + i] = __floats2half2_rn(f.x * inv, f.y * inv);
        }
    }
    __syncthreads();

    // ---- A@V phase ----
    float acc[2][2][4] = {};
    const int nvt = kend >> 5;
    for (int t = 0; t < nvt; t++) {
        stsV();
        __syncthreads();
        if (t + 1 < nvt) ldgV(t + 1);

        const int kb = t << 4;
#pragma unroll
        for (int c = 0; c < 2; c++) {
            uint32_t af[2][4];
#pragma unroll
            for (int mt = 0; mt < 2; mt++) {
                int r0 = wm*32 + mt*16 + g;
                af[mt][0] = *(const uint32_t*)&Ssm[r0*SSTR + kb + 8*c + tig];
                af[mt][1] = *(const uint32_t*)&Ssm[(r0 + 8)*SSTR + kb + 8*c + tig];
                af[mt][2] = *(const uint32_t*)&Ssm[r0*SSTR + kb + 8*c + 4 + tig];
                af[mt][3] = *(const uint32_t*)&Ssm[(r0 + 8)*SSTR + kb + 8*c + 4 + tig];
            }
            uint32_t bf[2][2];
#pragma unroll
            for (int nt = 0; nt < 2; nt++) {
                int n = wn*16 + nt*8 + g;
                bf[nt][0] = *(const uint32_t*)&Vs2[(8*c + tig)*72 + n];
                bf[nt][1] = *(const uint32_t*)&Vs2[(8*c + 4 + tig)*72 + n];
            }
#pragma unroll
            for (int mt = 0; mt < 2; mt++)
#pragma unroll
                for (int nt = 0; nt < 2; nt++)
                    mma_f16(acc[mt][nt], af[mt][0], af[mt][1], af[mt][2], af[mt][3],
                            bf[nt][0], bf[nt][1]);
        }
        __syncthreads();
    }

#pragma unroll
    for (int mt = 0; mt < 2; mt++) {
#pragma unroll
        for (int nt = 0; nt < 2; nt++) {
            int qr = wm*32 + mt*16 + g;
            int d  = wn*16 + nt*8 + 2*tig;
#pragma unroll
            for (int rr = 0; rr < 2; rr++) {
                size_t row = (size_t)b*cSQ + q0 + qr + rr*8;
                float2 v = { acc[mt][nt][rr*2 + 0], acc[mt][nt][rr*2 + 1] };
                *(float2*)&O[row*cD + h*cDK + d] = v;
            }
        }
    }
}
constexpr int SMEM_SELF = 64*260*4 + 2*(64*36*4) + 16*72*4;   // 89600

// ---------------------------------------------------------------------------
// Fused CROSS attention: 32 q-rows/block, kv-mask, coalesced P writeout,
// K/V register prefetch.
// ---------------------------------------------------------------------------
__global__ __launch_bounds__(256) void attn_cross_fused(
    const float* __restrict__ Q, const float* __restrict__ K,
    const float* __restrict__ V, const int* __restrict__ kvmask,
    float* __restrict__ P, float* __restrict__ O, float scale)
{
    constexpr int SSTR = 516;
    constexpr int SK = cSK;
    extern __shared__ char smraw[];
    __half2* Ssm    = (__half2*)(smraw);
    __half2* Qs2    = (__half2*)(smraw + 32*SSTR*4);
    __half2* Ks2    = (__half2*)(smraw + 32*SSTR*4 + 32*36*4);
    __half2* Vs2    = (__half2*)(smraw + 32*SSTR*4 + 32*36*4 + 64*36*4);
    int*     msk    = (int*)    (smraw + 32*SSTR*4 + 32*36*4 + 64*36*4 + 16*72*4);
    float*   rowInv = (float*)  (smraw + 32*SSTR*4 + 32*36*4 + 64*36*4 + 16*72*4 + 4096);

    const int bh = blockIdx.y;
    const int b  = bh >> 4, h = bh & 15;
    const int q0 = blockIdx.x * 32;
    const int tid  = threadIdx.x;
    const int warp = tid >> 5, lane = tid & 31;
    const int g = lane >> 2, tig = lane & 3;
    const int wm = warp >> 2;
    const int wn = warp & 3;

    const int r4 = tid >> 2, c4 = tid & 3;
    const float* Kbase = K + ((size_t)b*SK)*cD + h*cDK;
    const float* Vbase = V + ((size_t)b*SK)*cD + h*cDK;

    float4 pk0, pk1, pk2, pk3;
    auto ldgK = [&](int kt) {
        const float* kp = Kbase + (size_t)(kt*64 + r4)*cD + c4*16;
        pk0 = *(const float4*)(kp);     pk1 = *(const float4*)(kp + 4);
        pk2 = *(const float4*)(kp + 8); pk3 = *(const float4*)(kp + 12);
    };
    auto stsK = [&]() {
        *(uint4*)&Ks2[r4*36 + c4*8]     = pack8(pk0, pk1);
        *(uint4*)&Ks2[r4*36 + c4*8 + 4] = pack8(pk2, pk3);
    };

    ldgK(0);

    {
        const int r = tid >> 3, cq = tid & 7;
        const float* qp = Q + ((size_t)b*cSQ + q0 + r)*cD + h*cDK + cq*8;
        float4 v0 = *(const float4*)(qp), v1 = *(const float4*)(qp + 4);
        *(uint4*)&Qs2[r*36 + cq*4] = pack8(v0, v1);
    }
    for (int i = tid; i < SK; i += 256) msk[i] = kvmask[b*SK + i];

    // ---- QK^T phase ----
    const int nkt = SK >> 6;
    for (int kt = 0; kt < nkt; kt++) {
        stsK();
        __syncthreads();
        if (kt + 1 < nkt) ldgK(kt + 1);

        const int k0 = kt << 6;
        float acc[2][4] = {};
#pragma unroll
        for (int kk2 = 0; kk2 < 32; kk2 += 8) {
            uint32_t af[4];
            {
                int r0 = wm*16 + g;
                af[0] = *(const uint32_t*)&Qs2[r0*36 + kk2 + tig];
                af[1] = *(const uint32_t*)&Qs2[(r0 + 8)*36 + kk2 + tig];
                af[2] = *(const uint32_t*)&Qs2[r0*36 + kk2 + 4 + tig];
                af[3] = *(const uint32_t*)&Qs2[(r0 + 8)*36 + kk2 + 4 + tig];
            }
            uint32_t bf[2][2];
#pragma unroll
            for (int nt = 0; nt < 2; nt++) {
                int n = wn*16 + nt*8 + g;
                bf[nt][0] = *(const uint32_t*)&Ks2[n*36 + kk2 + tig];
                bf[nt][1] = *(const uint32_t*)&Ks2[n*36 + kk2 + 4 + tig];
            }
#pragma unroll
            for (int nt = 0; nt < 2; nt++)
                mma_f16(acc[nt], af[0], af[1], af[2], af[3], bf[nt][0], bf[nt][1]);
        }

#pragma unroll
        for (int nt = 0; nt < 2; nt++) {
            int qr = wm*16 + g;
            int kg = k0 + wn*16 + nt*8 + 2*tig;
            bool m0 = msk[kg] == 0;
            bool m1 = msk[kg + 1] == 0;
#pragma unroll
            for (int rr = 0; rr < 2; rr++) {
                float v0 = m0 ? -INFINITY : acc[nt][rr*2 + 0] * scale;
                float v1 = m1 ? -INFINITY : acc[nt][rr*2 + 1] * scale;
                Ssm[(qr + rr*8)*SSTR + (kg >> 1)] = __floats2half2_rn(v0, v1);
            }
        }
        __syncthreads();
    }

    const int vk2 = tid >> 4, vd = (tid & 15) << 2;
    float4 pv0, pv1;
    auto ldgV = [&](int t) {
        const float* vp = Vbase + (size_t)(t*32 + 2*vk2)*cD + vd;
        pv0 = *(const float4*)vp;
        pv1 = *(const float4*)(vp + cD);
    };
    auto stsV = [&]() {
        *(uint4*)&Vs2[vk2*72 + vd] = make_uint4(
            h2u(__floats2half2_rn(pv0.x, pv1.x)), h2u(__floats2half2_rn(pv0.y, pv1.y)),
            h2u(__floats2half2_rn(pv0.z, pv1.z)), h2u(__floats2half2_rn(pv0.w, pv1.w)));
    };

    ldgV(0);

    // ---- softmax: 8 lanes per row ----
    constexpr int kext2 = SK >> 1;
    {
        const int row = tid >> 3, l8 = tid & 7;
        float m = -INFINITY;
        for (int i = l8; i < kext2; i += 8) {
            float2 f = __half22float2(Ssm[row*SSTR + i]);
            m = fmaxf(m, fmaxf(f.x, f.y));
        }
        m = fmaxf(m, __shfl_xor_sync(0xffffffffu, m, 1));
        m = fmaxf(m, __shfl_xor_sync(0xffffffffu, m, 2));
        m = fmaxf(m, __shfl_xor_sync(0xffffffffu, m, 4));

        float s = 0.f;
        for (int i = l8; i < kext2; i += 8) {
            float2 f = __half22float2(Ssm[row*SSTR + i]);
            float e0 = __expf(f.x - m), e1 = __expf(f.y - m);
            s += e0 + e1;
            Ssm[row*SSTR + i] = __floats2half2_rn(e0, e1);
        }
        s += __shfl_xor_sync(0xffffffffu, s, 1);
        s += __shfl_xor_sync(0xffffffffu, s, 2);
        s += __shfl_xor_sync(0xffffffffu, s, 4);
        if (l8 == 0) rowInv[row] = 1.0f / s;
    }
    __syncthreads();

    // ---- normalize + coalesced P writeout (warp per row) ----
#pragma unroll
    for (int r = warp; r < 32; r += 8) {
        const float inv = rowInv[r];
        float* Prow = &P[((size_t)bh*cSQ + q0 + r)*SK];
        for (int i = lane; i < kext2; i += 32) {
            float2 f = __half22float2(Ssm[r*SSTR + i]);
            f.x *= inv; f.y *= inv;
            Ssm[r*SSTR + i] = __floats2half2_rn(f.x, f.y);
            *(float2*)&Prow[2*i] = f;
        }
    }
    __syncthreads();

    // ---- A@V phase ----
    float acc[2][4] = {};
    const int nvt = SK >> 5;
    for (int t = 0; t < nvt; t++) {
        stsV();
        __syncthreads();
        if (t + 1 < nvt) ldgV(t + 1);

        const int kb = t << 4;
#pragma unroll
        for (int c = 0; c < 2; c++) {
            uint32_t af[4];
            {
                int r0 = wm*16 + g;
                af[0] = *(const uint32_t*)&Ssm[r0*SSTR + kb + 8*c + tig];
                af[1] = *(const uint32_t*)&Ssm[(r0 + 8)*SSTR + kb + 8*c + tig];
                af[2] = *(const uint32_t*)&Ssm[r0*SSTR + kb + 8*c + 4 + tig];
                af[3] = *(const uint32_t*)&Ssm[(r0 + 8)*SSTR + kb + 8*c + 4 + tig];
            }
            uint32_t bf[2][2];
#pragma unroll
            for (int nt = 0; nt < 2; nt++) {
                int n = wn*16 + nt*8 + g;
                bf[nt][0] = *(const uint32_t*)&Vs2[(8*c + tig)*72 + n];
                bf[nt][1] = *(const uint32_t*)&Vs2[(8*c + 4 + tig)*72 + n];
            }
#pragma unroll
            for (int nt = 0; nt < 2; nt++)
                mma_f16(acc[nt], af[0], af[1], af[2], af[3], bf[nt][0], bf[nt][1]);
        }
        __syncthreads();
    }

#pragma unroll
    for (int nt = 0; nt < 2; nt++) {
        int qr = wm*16 + g;
        int d  = wn*16 + nt*8 + 2*tig;
#pragma unroll
        for (int rr = 0; rr < 2; rr++) {
            size_t row = (size_t)b*cSQ + q0 + qr + rr*8;
            float2 v = { acc[nt][rr*2 + 0], acc[nt][rr*2 + 1] };
            *(float2*)&O[row*cD + h*cDK + d] = v;
        }
    }
}
constexpr int SMEM_CROSS = 32*516*4 + 32*36*4 + 64*36*4 + 16*72*4 + 4096 + 128;  // 88704

// ---------------------------------------------------------------------------
// out = LayerNorm(X + R) * g + b, D=1024. Shuffle reductions, 2 syncs.
// ---------------------------------------------------------------------------
__global__ __launch_bounds__(256) void ln_residual_kernel(
    const float* __restrict__ X, const float* __restrict__ R,
    const float* __restrict__ g, const float* __restrict__ be,
    float* __restrict__ out)
{
    __shared__ float redm[8];
    __shared__ float redv[8];
    const size_t row = blockIdx.x;
    const int t = threadIdx.x;
    const int warp = t >> 5, lane = t & 31;
    const float* xr = X + row*cD;
    const float* rr = R + row*cD;

    float v[4]; float s = 0.f;
#pragma unroll
    for (int i = 0; i < 4; i++) { v[i] = xr[t + i*256] + rr[t + i*256]; s += v[i]; }
#pragma unroll
    for (int off = 16; off > 0; off >>= 1)
        s += __shfl_xor_sync(0xffffffffu, s, off);
    if (lane == 0) redm[warp] = s;
    __syncthreads();
    float mu = redm[0];
#pragma unroll
    for (int i = 1; i < 8; i++) mu += redm[i];
    mu *= (1.0f / cD);

    float vs = 0.f;
#pragma unroll
    for (int i = 0; i < 4; i++) { float d = v[i] - mu; vs += d*d; }
#pragma unroll
    for (int off = 16; off > 0; off >>= 1)
        vs += __shfl_xor_sync(0xffffffffu, vs, off);
    if (lane == 0) redv[warp] = vs;
    __syncthreads();
    float var = redv[0];
#pragma unroll
    for (int i = 1; i < 8; i++) var += redv[i];
    float inv = rsqrtf(var * (1.0f / cD) + 1e-5f);

    float* orow = out + row*cD;
#pragma unroll
    for (int i = 0; i < 4; i++) {
        int c = t + i*256;
        orow[c] = (v[i] - mu) * inv * g[c] + be[c];
    }
}

// ---------------------------------------------------------------------------
// Launch
// ---------------------------------------------------------------------------
extern "C" void kernel_launch(void* const* d_in, const int* in_sizes, int n_in,
                              void* d_out, int out_size)
{
    const float* x        = (const float*)d_in[0];
    const float* enc_o    = (const float*)d_in[1];
    const int*   enc_mask = (const int*)  d_in[2];
    const float* a1_wq = (const float*)d_in[3];
    const float* a1_bq = (const float*)d_in[4];
    const float* a1_wk = (const float*)d_in[5];
    const float* a1_bk = (const float*)d_in[6];
    const float* a1_wv = (const float*)d_in[7];
    const float* a1_bv = (const float*)d_in[8];
    const float* a1_wo = (const float*)d_in[9];
    const float* a1_bo = (const float*)d_in[10];
    const float* a2_wq = (const float*)d_in[11];
    const float* a2_bq = (const float*)d_in[12];
    const float* a2_wk = (const float*)d_in[13];
    const float* a2_bk = (const float*)d_in[14];
    const float* a2_wv = (const float*)d_in[15];
    const float* a2_bv = (const float*)d_in[16];
    const float* a2_wo = (const float*)d_in[17];
    const float* a2_bo = (const float*)d_in[18];
    const float* ff_w1 = (const float*)d_in[19];
    const float* ff_b1 = (const float*)d_in[20];
    const float* ff_w2 = (const float*)d_in[21];
    const float* ff_b2 = (const float*)d_in[22];
    const float* ln1_g = (const float*)d_in[23];
    const float* ln1_b = (const float*)d_in[24];
    const float* ln2_g = (const float*)d_in[25];
    const float* ln2_b = (const float*)d_in[26];
    const float* ln3_g = (const float*)d_in[27];
    const float* ln3_b = (const float*)d_in[28];

    float* out_x    = (float*)d_out;
    float* out_attn = out_x + (size_t)cB*cSQ*cD;

    float *bufQ, *bufK, *bufV, *bufC, *bufO, *bufX1, *bufX2, *bufF;
    cudaGetSymbolAddress((void**)&bufQ,  g_bufQ);
    cudaGetSymbolAddress((void**)&bufK,  g_bufK);
    cudaGetSymbolAddress((void**)&bufV,  g_bufV);
    cudaGetSymbolAddress((void**)&bufC,  g_bufC);
    cudaGetSymbolAddress((void**)&bufO,  g_bufO);
    cudaGetSymbolAddress((void**)&bufX1, g_bufX1);
    cudaGetSymbolAddress((void**)&bufX2, g_bufX2);
    cudaGetSymbolAddress((void**)&bufF,  g_bufF);

    cudaFuncSetAttribute(attn_self_fused,
                         cudaFuncAttributeMaxDynamicSharedMemorySize, SMEM_SELF);
    cudaFuncSetAttribute(attn_cross_fused,
                         cudaFuncAttributeMaxDynamicSharedMemorySize, SMEM_CROSS);

    const float scale = 0.125f;   // 1/sqrt(64)
    const dim3 blk(256);
    const int M1 = cB * cSQ;      // 4096
    const int M2 = cB * cSK;      // 8192

    // ---- self-attention (causal, fused) ----
    gemm_fp16<false><<<dim3(cD/128, M1/128, 3), blk>>>(
        x, mkset(a1_wq, a1_bq, bufQ, a1_wk, a1_bk, bufK, a1_wv, a1_bv, bufV),
        M1, cD, cD);
    attn_self_fused<<<dim3(cSQ/64, cB*cH), blk, SMEM_SELF>>>(
        bufQ, bufK, bufV, bufC, scale);
    gemm_fp16<false><<<dim3(cD/128, M1/128, 1), blk>>>(
        bufC, mkset(a1_wo, a1_bo, bufO), M1, cD, cD);
    ln_residual_kernel<<<M1, blk>>>(x, bufO, ln1_g, ln1_b, bufX1);

    // ---- cross-attention (kv mask, fused; P streamed to d_out) ----
    gemm_fp16<false><<<dim3(cD/128, M1/128, 1), blk>>>(
        bufX1, mkset(a2_wq, a2_bq, bufQ), M1, cD, cD);
    gemm_fp16<false><<<dim3(cD/128, M2/128, 2), blk>>>(
        enc_o, mkset(a2_wk, a2_bk, bufK, a2_wv, a2_bv, bufV), M2, cD, cD);
    attn_cross_fused<<<dim3(cSQ/32, cB*cH), blk, SMEM_CROSS>>>(
        bufQ, bufK, bufV, enc_mask, out_attn, bufC, scale);
    gemm_fp16<false><<<dim3(cD/128, M1/128, 1), blk>>>(
        bufC, mkset(a2_wo, a2_bo, bufO), M1, cD, cD);
    ln_residual_kernel<<<M1, blk>>>(bufX1, bufO, ln2_g, ln2_b, bufX2);

    // ---- feed-forward ----
    gemm_fp16<true ><<<dim3(cF/128, M1/128, 1), blk>>>(
        bufX2, mkset(ff_w1, ff_b1, bufF), M1, cF, cD);
    gemm_fp16<false><<<dim3(cD/128, M1/128, 1), blk>>>(
        bufF, mkset(ff_w2, ff_b2, bufO), M1, cD, cF);
    ln_residual_kernel<<<M1, blk>>>(bufX2, bufO, ln3_g, ln3_b, out_x);
}

// round 14
// speedup vs baseline: 1.2276x; 1.0263x over previous
#include <cuda_runtime.h>
#include <cuda_fp16.h>
#include <math.h>
#include <stdint.h>

// Problem constants
constexpr int cB  = 8;
constexpr int cSQ = 512;
constexpr int cSK = 1024;
constexpr int cD  = 1024;
constexpr int cH  = 16;
constexpr int cDK = 64;
constexpr int cF  = 4096;

// ---------------------------------------------------------------------------
// Scratch (device globals; no allocations allowed)
// ---------------------------------------------------------------------------
__device__ float g_bufQ [(size_t)cB*cSQ*cD];
__device__ float g_bufK [(size_t)cB*cSQ*cD];    // self K (SQ rows)
__device__ float g_bufV [(size_t)cB*cSQ*cD];    // self V
__device__ float g_bufK2[(size_t)cB*cSK*cD];    // cross K (SK rows)
__device__ float g_bufV2[(size_t)cB*cSK*cD];    // cross V
__device__ float g_bufC [(size_t)cB*cSQ*cD];
__device__ float g_bufO [(size_t)cB*cSQ*cD];
__device__ float g_bufX1[(size_t)cB*cSQ*cD];
__device__ float g_bufX2[(size_t)cB*cSQ*cD];
__device__ float g_bufF [(size_t)cB*cSQ*cF];

// ---------------------------------------------------------------------------
// helpers
// ---------------------------------------------------------------------------
__device__ __forceinline__ void mma_f16(float c[4],
    uint32_t a0, uint32_t a1, uint32_t a2, uint32_t a3,
    uint32_t b0, uint32_t b1)
{
    asm volatile(
        "mma.sync.aligned.m16n8k16.row.col.f32.f16.f16.f32 "
        "{%0,%1,%2,%3}, {%4,%5,%6,%7}, {%8,%9}, {%0,%1,%2,%3};"
        : "+f"(c[0]), "+f"(c[1]), "+f"(c[2]), "+f"(c[3])
        : "r"(a0), "r"(a1), "r"(a2), "r"(a3), "r"(b0), "r"(b1));
}

__device__ __forceinline__ uint32_t h2u(__half2 h) {
    return *reinterpret_cast<uint32_t*>(&h);
}

__device__ __forceinline__ uint4 pack8(float4 a, float4 b) {
    return make_uint4(
        h2u(__floats2half2_rn(a.x, a.y)), h2u(__floats2half2_rn(a.z, a.w)),
        h2u(__floats2half2_rn(b.x, b.y)), h2u(__floats2half2_rn(b.z, b.w)));
}

// Pointer set for multi-output GEMM (blockIdx.z selects)
struct GemmSet {
    const float* W[3];
    const float* bias[3];
    float*       C[3];
};

// ---------------------------------------------------------------------------
// fp16 GEMM (proven body): C[M,N] = A[M,K] @ W[K,N] + bias (+ReLU).
// blockIdx.z selects (W, bias, C) -> sibling GEMMs in one launch.
// ---------------------------------------------------------------------------
template<bool RELU>
__global__ __launch_bounds__(256, 2) void gemm_fp16(
    const float* __restrict__ A, GemmSet set,
    int M, int N, int K)
{
    const float* __restrict__ W    = set.W[blockIdx.z];
    const float* __restrict__ bias = set.bias[blockIdx.z];
    float* __restrict__       C    = set.C[blockIdx.z];

    __shared__ __half2 As2[128 * 12];
    __shared__ __half2 Bs2[8 * 136];

    const int tid  = threadIdx.x;
    const int bx   = blockIdx.x, by = blockIdx.y;
    const int warp = tid >> 5, lane = tid & 31;
    const int g = lane >> 2, tig = lane & 3;
    const int wm = warp >> 2;
    const int wn = warp & 3;

    const int ar  = tid >> 1;
    const int ac2 = (tid & 1) * 4;
    const float* Asrc = A + (size_t)(by*128 + ar)*K + ac2*2;

    const int bk2 = warp;
    const int bn  = lane * 4;
    const float* Bsrc0 = W + (size_t)(2*bk2    )*N + bx*128 + bn;
    const float* Bsrc1 = W + (size_t)(2*bk2 + 1)*N + bx*128 + bn;

    const int nk = K >> 4;
    float acc[4][4][4] = {};

    float4 pa0 = *(const float4*)(Asrc);
    float4 pa1 = *(const float4*)(Asrc + 4);
    float4 pb0 = *(const float4*)(Bsrc0);
    float4 pb1 = *(const float4*)(Bsrc1);

    for (int kt = 0; kt < nk; kt++) {
        {
            *(uint4*)&As2[ar*12 + ac2] = pack8(pa0, pa1);
            __half2 b0 = __floats2half2_rn(pb0.x, pb1.x);
            __half2 b1 = __floats2half2_rn(pb0.y, pb1.y);
            __half2 b2 = __floats2half2_rn(pb0.z, pb1.z);
            __half2 b3 = __floats2half2_rn(pb0.w, pb1.w);
            *(uint4*)&Bs2[bk2*136 + bn] = make_uint4(h2u(b0), h2u(b1), h2u(b2), h2u(b3));
        }
        __syncthreads();

        if (kt + 1 < nk) {
            const int kn = (kt + 1) << 4;
            pa0 = *(const float4*)(Asrc + kn);
            pa1 = *(const float4*)(Asrc + kn + 4);
            pb0 = *(const float4*)(Bsrc0 + (size_t)kn*N);
            pb1 = *(const float4*)(Bsrc1 + (size_t)kn*N);
        }

        uint32_t af[4][4];
#pragma unroll
        for (int mt = 0; mt < 4; mt++) {
            int r0 = wm*64 + mt*16 + g;
            af[mt][0] = *(uint32_t*)&As2[r0*12 + tig];
            af[mt][1] = *(uint32_t*)&As2[(r0 + 8)*12 + tig];
            af[mt][2] = *(uint32_t*)&As2[r0*12 + 4 + tig];
            af[mt][3] = *(uint32_t*)&As2[(r0 + 8)*12 + 4 + tig];
        }
        uint32_t bf[4][2];
#pragma unroll
        for (int nt = 0; nt < 4; nt++) {
            int n = wn*32 + nt*8 + g;
            bf[nt][0] = *(uint32_t*)&Bs2[tig*136 + n];
            bf[nt][1] = *(uint32_t*)&Bs2[(4 + tig)*136 + n];
        }
#pragma unroll
        for (int mt = 0; mt < 4; mt++)
#pragma unroll
            for (int nt = 0; nt < 4; nt++)
                mma_f16(acc[mt][nt], af[mt][0], af[mt][1], af[mt][2], af[mt][3],
                        bf[nt][0], bf[nt][1]);
        __syncthreads();
    }

#pragma unroll
    for (int mt = 0; mt < 4; mt++) {
#pragma unroll
        for (int nt = 0; nt < 4; nt++) {
            int row0 = by*128 + wm*64 + mt*16 + g;
            int col  = bx*128 + wn*32 + nt*8 + 2*tig;
            float b0 = bias[col], b1 = bias[col + 1];
            float2 v0 = { acc[mt][nt][0] + b0, acc[mt][nt][1] + b1 };
            float2 v1 = { acc[mt][nt][2] + b0, acc[mt][nt][3] + b1 };
            if (RELU) {
                v0.x = fmaxf(v0.x, 0.f); v0.y = fmaxf(v0.y, 0.f);
                v1.x = fmaxf(v1.x, 0.f); v1.y = fmaxf(v1.y, 0.f);
            }
            *(float2*)&C[(size_t)row0*N + col]       = v0;
            *(float2*)&C[(size_t)(row0 + 8)*N + col] = v1;
        }
    }
}

static inline GemmSet mkset(const float* w0, const float* b0, float* c0,
                            const float* w1 = nullptr, const float* b1 = nullptr, float* c1 = nullptr,
                            const float* w2 = nullptr, const float* b2 = nullptr, float* c2 = nullptr)
{
    GemmSet s;
    s.W[0] = w0; s.bias[0] = b0; s.C[0] = c0;
    s.W[1] = w1; s.bias[1] = b1; s.C[1] = c1;
    s.W[2] = w2; s.bias[2] = b2; s.C[2] = c2;
    return s;
}

// ---------------------------------------------------------------------------
// Fused SELF attention (causal): 64 q-rows/block, K/V register prefetch.
// ---------------------------------------------------------------------------
__global__ __launch_bounds__(256) void attn_self_fused(
    const float* __restrict__ Q, const float* __restrict__ K,
    const float* __restrict__ V, float* __restrict__ O, float scale)
{
    constexpr int SSTR = 260;
    extern __shared__ char smraw[];
    __half2* Ssm = (__half2*)(smraw);
    __half2* Qs2 = (__half2*)(smraw + 64*SSTR*4);
    __half2* Ks2 = (__half2*)(smraw + 64*SSTR*4 + 64*36*4);
    __half2* Vs2 = (__half2*)(smraw + 64*SSTR*4 + 2*64*36*4);

    const int bh = blockIdx.y;
    const int b  = bh >> 4, h = bh & 15;
    const int q0 = (gridDim.x - 1 - blockIdx.x) * 64;   // heavy blocks first
    const int tid  = threadIdx.x;
    const int warp = tid >> 5, lane = tid & 31;
    const int g = lane >> 2, tig = lane & 3;
    const int wm = warp >> 2;
    const int wn = warp & 3;

    const int kend = q0 + 64;
    const int r4 = tid >> 2, c4 = tid & 3;

    const float* Kbase = K + ((size_t)b*cSQ)*cD + h*cDK;
    const float* Vbase = V + ((size_t)b*cSQ)*cD + h*cDK;

    float4 pk0, pk1, pk2, pk3;
    auto ldgK = [&](int kt) {
        const float* kp = Kbase + (size_t)(kt*64 + r4)*cD + c4*16;
        pk0 = *(const float4*)(kp);     pk1 = *(const float4*)(kp + 4);
        pk2 = *(const float4*)(kp + 8); pk3 = *(const float4*)(kp + 12);
    };
    auto stsK = [&]() {
        *(uint4*)&Ks2[r4*36 + c4*8]     = pack8(pk0, pk1);
        *(uint4*)&Ks2[r4*36 + c4*8 + 4] = pack8(pk2, pk3);
    };

    ldgK(0);

    {
        const float* qp = Q + ((size_t)b*cSQ + q0 + r4)*cD + h*cDK + c4*16;
        float4 v0 = *(const float4*)(qp),     v1 = *(const float4*)(qp + 4);
        float4 v2 = *(const float4*)(qp + 8), v3 = *(const float4*)(qp + 12);
        *(uint4*)&Qs2[r4*36 + c4*8]     = pack8(v0, v1);
        *(uint4*)&Qs2[r4*36 + c4*8 + 4] = pack8(v2, v3);
    }

    const int nkt = kend >> 6;
    for (int kt = 0; kt < nkt; kt++) {
        stsK();
        __syncthreads();
        if (kt + 1 < nkt) ldgK(kt + 1);

        const int k0 = kt << 6;
        float acc[2][2][4] = {};
#pragma unroll
        for (int kk2 = 0; kk2 < 32; kk2 += 8) {
            uint32_t af[2][4];
#pragma unroll
            for (int mt = 0; mt < 2; mt++) {
                int r0 = wm*32 + mt*16 + g;
                af[mt][0] = *(const uint32_t*)&Qs2[r0*36 + kk2 + tig];
                af[mt][1] = *(const uint32_t*)&Qs2[(r0 + 8)*36 + kk2 + tig];
                af[mt][2] = *(const uint32_t*)&Qs2[r0*36 + kk2 + 4 + tig];
                af[mt][3] = *(const uint32_t*)&Qs2[(r0 + 8)*36 + kk2 + 4 + tig];
            }
            uint32_t bf[2][2];
#pragma unroll
            for (int nt = 0; nt < 2; nt++) {
                int n = wn*16 + nt*8 + g;
                bf[nt][0] = *(const uint32_t*)&Ks2[n*36 + kk2 + tig];
                bf[nt][1] = *(const uint32_t*)&Ks2[n*36 + kk2 + 4 + tig];
            }
#pragma unroll
            for (int mt = 0; mt < 2; mt++)
#pragma unroll
                for (int nt = 0; nt < 2; nt++)
                    mma_f16(acc[mt][nt], af[mt][0], af[mt][1], af[mt][2], af[mt][3],
                            bf[nt][0], bf[nt][1]);
        }

#pragma unroll
        for (int mt = 0; mt < 2; mt++) {
#pragma unroll
            for (int nt = 0; nt < 2; nt++) {
                int qr = wm*32 + mt*16 + g;
                int kg = k0 + wn*16 + nt*8 + 2*tig;
#pragma unroll
                for (int rr = 0; rr < 2; rr++) {
                    int q = q0 + qr + rr*8;
                    float v0 = acc[mt][nt][rr*2 + 0] * scale;
                    float v1 = acc[mt][nt][rr*2 + 1] * scale;
                    if (kg     > q) v0 = -INFINITY;
                    if (kg + 1 > q) v1 = -INFINITY;
                    Ssm[(qr + rr*8)*SSTR + (kg >> 1)] = __floats2half2_rn(v0, v1);
                }
            }
        }
        __syncthreads();
    }

    const int vk2 = tid >> 4, vd = (tid & 15) << 2;
    float4 pv0, pv1;
    auto ldgV = [&](int t) {
        const float* vp = Vbase + (size_t)(t*32 + 2*vk2)*cD + vd;
        pv0 = *(const float4*)vp;
        pv1 = *(const float4*)(vp + cD);
    };
    auto stsV = [&]() {
        *(uint4*)&Vs2[vk2*72 + vd] = make_uint4(
            h2u(__floats2half2_rn(pv0.x, pv1.x)), h2u(__floats2half2_rn(pv0.y, pv1.y)),
            h2u(__floats2half2_rn(pv0.z, pv1.z)), h2u(__floats2half2_rn(pv0.w, pv1.w)));
    };

    ldgV(0);

    const int kext2 = kend >> 1;
    {
        const int row = tid >> 2, qg = tid & 3;
        float m = -INFINITY;
        for (int i = qg; i < kext2; i += 4) {
            float2 f = __half22float2(Ssm[row*SSTR + i]);
            m = fmaxf(m, fmaxf(f.x, f.y));
        }
        m = fmaxf(m, __shfl_xor_sync(0xffffffffu, m, 1));
        m = fmaxf(m, __shfl_xor_sync(0xffffffffu, m, 2));

        float s = 0.f;
        for (int i = qg; i < kext2; i += 4) {
            float2 f = __half22float2(Ssm[row*SSTR + i]);
            float e0 = __expf(f.x - m), e1 = __expf(f.y - m);
            s += e0 + e1;
            Ssm[row*SSTR + i] = __floats2half2_rn(e0, e1);
        }
        s += __shfl_xor_sync(0xffffffffu, s, 1);
        s += __shfl_xor_sync(0xffffffffu, s, 2);
        const float inv = 1.0f / s;

        for (int i = qg; i < kext2; i += 4) {
            float2 f = __half22float2(Ssm[row*SSTR + i]);
            Ssm[row*SSTR + i] = __floats2half2_rn(f.x * inv, f.y * inv);
        }
    }
    __syncthreads();

    float acc[2][2][4] = {};
    const int nvt = kend >> 5;
    for (int t = 0; t < nvt; t++) {
        stsV();
        __syncthreads();
        if (t + 1 < nvt) ldgV(t + 1);

        const int kb = t << 4;
#pragma unroll
        for (int c = 0; c < 2; c++) {
            uint32_t af[2][4];
#pragma unroll
            for (int mt = 0; mt < 2; mt++) {
                int r0 = wm*32 + mt*16 + g;
                af[mt][0] = *(const uint32_t*)&Ssm[r0*SSTR + kb + 8*c + tig];
                af[mt][1] = *(const uint32_t*)&Ssm[(r0 + 8)*SSTR + kb + 8*c + tig];
                af[mt][2] = *(const uint32_t*)&Ssm[r0*SSTR + kb + 8*c + 4 + tig];
                af[mt][3] = *(const uint32_t*)&Ssm[(r0 + 8)*SSTR + kb + 8*c + 4 + tig];
            }
            uint32_t bf[2][2];
#pragma unroll
            for (int nt = 0; nt < 2; nt++) {
                int n = wn*16 + nt*8 + g;
                bf[nt][0] = *(const uint32_t*)&Vs2[(8*c + tig)*72 + n];
                bf[nt][1] = *(const uint32_t*)&Vs2[(8*c + 4 + tig)*72 + n];
            }
#pragma unroll
            for (int mt = 0; mt < 2; mt++)
#pragma unroll
                for (int nt = 0; nt < 2; nt++)
                    mma_f16(acc[mt][nt], af[mt][0], af[mt][1], af[mt][2], af[mt][3],
                            bf[nt][0], bf[nt][1]);
        }
        __syncthreads();
    }

#pragma unroll
    for (int mt = 0; mt < 2; mt++) {
#pragma unroll
        for (int nt = 0; nt < 2; nt++) {
            int qr = wm*32 + mt*16 + g;
            int d  = wn*16 + nt*8 + 2*tig;
#pragma unroll
            for (int rr = 0; rr < 2; rr++) {
                size_t row = (size_t)b*cSQ + q0 + qr + rr*8;
                float2 v = { acc[mt][nt][rr*2 + 0], acc[mt][nt][rr*2 + 1] };
                *(float2*)&O[row*cD + h*cDK + d] = v;
            }
        }
    }
}
constexpr int SMEM_SELF = 64*260*4 + 2*(64*36*4) + 16*72*4;   // 89600

// ---------------------------------------------------------------------------
// Fused CROSS attention: 32 q-rows/block, kv-mask, coalesced P writeout,
// K/V register prefetch.
// ---------------------------------------------------------------------------
__global__ __launch_bounds__(256) void attn_cross_fused(
    const float* __restrict__ Q, const float* __restrict__ K,
    const float* __restrict__ V, const int* __restrict__ kvmask,
    float* __restrict__ P, float* __restrict__ O, float scale)
{
    constexpr int SSTR = 516;
    constexpr int SK = cSK;
    extern __shared__ char smraw[];
    __half2* Ssm    = (__half2*)(smraw);
    __half2* Qs2    = (__half2*)(smraw + 32*SSTR*4);
    __half2* Ks2    = (__half2*)(smraw + 32*SSTR*4 + 32*36*4);
    __half2* Vs2    = (__half2*)(smraw + 32*SSTR*4 + 32*36*4 + 64*36*4);
    int*     msk    = (int*)    (smraw + 32*SSTR*4 + 32*36*4 + 64*36*4 + 16*72*4);
    float*   rowInv = (float*)  (smraw + 32*SSTR*4 + 32*36*4 + 64*36*4 + 16*72*4 + 4096);

    const int bh = blockIdx.y;
    const int b  = bh >> 4, h = bh & 15;
    const int q0 = blockIdx.x * 32;
    const int tid  = threadIdx.x;
    const int warp = tid >> 5, lane = tid & 31;
    const int g = lane >> 2, tig = lane & 3;
    const int wm = warp >> 2;
    const int wn = warp & 3;

    const int r4 = tid >> 2, c4 = tid & 3;
    const float* Kbase = K + ((size_t)b*SK)*cD + h*cDK;
    const float* Vbase = V + ((size_t)b*SK)*cD + h*cDK;

    float4 pk0, pk1, pk2, pk3;
    auto ldgK = [&](int kt) {
        const float* kp = Kbase + (size_t)(kt*64 + r4)*cD + c4*16;
        pk0 = *(const float4*)(kp);     pk1 = *(const float4*)(kp + 4);
        pk2 = *(const float4*)(kp + 8); pk3 = *(const float4*)(kp + 12);
    };
    auto stsK = [&]() {
        *(uint4*)&Ks2[r4*36 + c4*8]     = pack8(pk0, pk1);
        *(uint4*)&Ks2[r4*36 + c4*8 + 4] = pack8(pk2, pk3);
    };

    ldgK(0);

    {
        const int r = tid >> 3, cq = tid & 7;
        const float* qp = Q + ((size_t)b*cSQ + q0 + r)*cD + h*cDK + cq*8;
        float4 v0 = *(const float4*)(qp), v1 = *(const float4*)(qp + 4);
        *(uint4*)&Qs2[r*36 + cq*4] = pack8(v0, v1);
    }
    for (int i = tid; i < SK; i += 256) msk[i] = kvmask[b*SK + i];

    const int nkt = SK >> 6;
    for (int kt = 0; kt < nkt; kt++) {
        stsK();
        __syncthreads();
        if (kt + 1 < nkt) ldgK(kt + 1);

        const int k0 = kt << 6;
        float acc[2][4] = {};
#pragma unroll
        for (int kk2 = 0; kk2 < 32; kk2 += 8) {
            uint32_t af[4];
            {
                int r0 = wm*16 + g;
                af[0] = *(const uint32_t*)&Qs2[r0*36 + kk2 + tig];
                af[1] = *(const uint32_t*)&Qs2[(r0 + 8)*36 + kk2 + tig];
                af[2] = *(const uint32_t*)&Qs2[r0*36 + kk2 + 4 + tig];
                af[3] = *(const uint32_t*)&Qs2[(r0 + 8)*36 + kk2 + 4 + tig];
            }
            uint32_t bf[2][2];
#pragma unroll
            for (int nt = 0; nt < 2; nt++) {
                int n = wn*16 + nt*8 + g;
                bf[nt][0] = *(const uint32_t*)&Ks2[n*36 + kk2 + tig];
                bf[nt][1] = *(const uint32_t*)&Ks2[n*36 + kk2 + 4 + tig];
            }
#pragma unroll
            for (int nt = 0; nt < 2; nt++)
                mma_f16(acc[nt], af[0], af[1], af[2], af[3], bf[nt][0], bf[nt][1]);
        }

#pragma unroll
        for (int nt = 0; nt < 2; nt++) {
            int qr = wm*16 + g;
            int kg = k0 + wn*16 + nt*8 + 2*tig;
            bool m0 = msk[kg] == 0;
            bool m1 = msk[kg + 1] == 0;
#pragma unroll
            for (int rr = 0; rr < 2; rr++) {
                float v0 = m0 ? -INFINITY : acc[nt][rr*2 + 0] * scale;
                float v1 = m1 ? -INFINITY : acc[nt][rr*2 + 1] * scale;
                Ssm[(qr + rr*8)*SSTR + (kg >> 1)] = __floats2half2_rn(v0, v1);
            }
        }
        __syncthreads();
    }

    const int vk2 = tid >> 4, vd = (tid & 15) << 2;
    float4 pv0, pv1;
    auto ldgV = [&](int t) {
        const float* vp = Vbase + (size_t)(t*32 + 2*vk2)*cD + vd;
        pv0 = *(const float4*)vp;
        pv1 = *(const float4*)(vp + cD);
    };
    auto stsV = [&]() {
        *(uint4*)&Vs2[vk2*72 + vd] = make_uint4(
            h2u(__floats2half2_rn(pv0.x, pv1.x)), h2u(__floats2half2_rn(pv0.y, pv1.y)),
            h2u(__floats2half2_rn(pv0.z, pv1.z)), h2u(__floats2half2_rn(pv0.w, pv1.w)));
    };

    ldgV(0);

    constexpr int kext2 = SK >> 1;
    {
        const int row = tid >> 3, l8 = tid & 7;
        float m = -INFINITY;
        for (int i = l8; i < kext2; i += 8) {
            float2 f = __half22float2(Ssm[row*SSTR + i]);
            m = fmaxf(m, fmaxf(f.x, f.y));
        }
        m = fmaxf(m, __shfl_xor_sync(0xffffffffu, m, 1));
        m = fmaxf(m, __shfl_xor_sync(0xffffffffu, m, 2));
        m = fmaxf(m, __shfl_xor_sync(0xffffffffu, m, 4));

        float s = 0.f;
        for (int i = l8; i < kext2; i += 8) {
            float2 f = __half22float2(Ssm[row*SSTR + i]);
            float e0 = __expf(f.x - m), e1 = __expf(f.y - m);
            s += e0 + e1;
            Ssm[row*SSTR + i] = __floats2half2_rn(e0, e1);
        }
        s += __shfl_xor_sync(0xffffffffu, s, 1);
        s += __shfl_xor_sync(0xffffffffu, s, 2);
        s += __shfl_xor_sync(0xffffffffu, s, 4);
        if (l8 == 0) rowInv[row] = 1.0f / s;
    }
    __syncthreads();

#pragma unroll
    for (int r = warp; r < 32; r += 8) {
        const float inv = rowInv[r];
        float* Prow = &P[((size_t)bh*cSQ + q0 + r)*SK];
        for (int i = lane; i < kext2; i += 32) {
            float2 f = __half22float2(Ssm[r*SSTR + i]);
            f.x *= inv; f.y *= inv;
            Ssm[r*SSTR + i] = __floats2half2_rn(f.x, f.y);
            *(float2*)&Prow[2*i] = f;
        }
    }
    __syncthreads();

    float acc[2][4] = {};
    const int nvt = SK >> 5;
    for (int t = 0; t < nvt; t++) {
        stsV();
        __syncthreads();
        if (t + 1 < nvt) ldgV(t + 1);

        const int kb = t << 4;
#pragma unroll
        for (int c = 0; c < 2; c++) {
            uint32_t af[4];
            {
                int r0 = wm*16 + g;
                af[0] = *(const uint32_t*)&Ssm[r0*SSTR + kb + 8*c + tig];
                af[1] = *(const uint32_t*)&Ssm[(r0 + 8)*SSTR + kb + 8*c + tig];
                af[2] = *(const uint32_t*)&Ssm[r0*SSTR + kb + 8*c + 4 + tig];
                af[3] = *(const uint32_t*)&Ssm[(r0 + 8)*SSTR + kb + 8*c + 4 + tig];
            }
            uint32_t bf[2][2];
#pragma unroll
            for (int nt = 0; nt < 2; nt++) {
                int n = wn*16 + nt*8 + g;
                bf[nt][0] = *(const uint32_t*)&Vs2[(8*c + tig)*72 + n];
                bf[nt][1] = *(const uint32_t*)&Vs2[(8*c + 4 + tig)*72 + n];
            }
#pragma unroll
            for (int nt = 0; nt < 2; nt++)
                mma_f16(acc[nt], af[0], af[1], af[2], af[3], bf[nt][0], bf[nt][1]);
        }
        __syncthreads();
    }

#pragma unroll
    for (int nt = 0; nt < 2; nt++) {
        int qr = wm*16 + g;
        int d  = wn*16 + nt*8 + 2*tig;
#pragma unroll
        for (int rr = 0; rr < 2; rr++) {
            size_t row = (size_t)b*cSQ + q0 + qr + rr*8;
            float2 v = { acc[nt][rr*2 + 0], acc[nt][rr*2 + 1] };
            *(float2*)&O[row*cD + h*cDK + d] = v;
        }
    }
}
constexpr int SMEM_CROSS = 32*516*4 + 32*36*4 + 64*36*4 + 16*72*4 + 4096 + 128;  // 88704

// ---------------------------------------------------------------------------
// out = LayerNorm(X + R) * g + b, D=1024. Shuffle reductions, 2 syncs.
// ---------------------------------------------------------------------------
__global__ __launch_bounds__(256) void ln_residual_kernel(
    const float* __restrict__ X, const float* __restrict__ R,
    const float* __restrict__ g, const float* __restrict__ be,
    float* __restrict__ out)
{
    __shared__ float redm[8];
    __shared__ float redv[8];
    const size_t row = blockIdx.x;
    const int t = threadIdx.x;
    const int warp = t >> 5, lane = t & 31;
    const float* xr = X + row*cD;
    const float* rr = R + row*cD;

    float v[4]; float s = 0.f;
#pragma unroll
    for (int i = 0; i < 4; i++) { v[i] = xr[t + i*256] + rr[t + i*256]; s += v[i]; }
#pragma unroll
    for (int off = 16; off > 0; off >>= 1)
        s += __shfl_xor_sync(0xffffffffu, s, off);
    if (lane == 0) redm[warp] = s;
    __syncthreads();
    float mu = redm[0];
#pragma unroll
    for (int i = 1; i < 8; i++) mu += redm[i];
    mu *= (1.0f / cD);

    float vs = 0.f;
#pragma unroll
    for (int i = 0; i < 4; i++) { float d = v[i] - mu; vs += d*d; }
#pragma unroll
    for (int off = 16; off > 0; off >>= 1)
        vs += __shfl_xor_sync(0xffffffffu, vs, off);
    if (lane == 0) redv[warp] = vs;
    __syncthreads();
    float var = redv[0];
#pragma unroll
    for (int i = 1; i < 8; i++) var += redv[i];
    float inv = rsqrtf(var * (1.0f / cD) + 1e-5f);

    float* orow = out + row*cD;
#pragma unroll
    for (int i = 0; i < 4; i++) {
        int c = t + i*256;
        orow[c] = (v[i] - mu) * inv * g[c] + be[c];
    }
}

// ---------------------------------------------------------------------------
// Side-stream handles (created lazily once; host-side only, no device mem)
// ---------------------------------------------------------------------------
static cudaStream_t g_s2 = nullptr;
static cudaEvent_t  g_evFork = nullptr, g_evJoin = nullptr;

// ---------------------------------------------------------------------------
// Launch
// ---------------------------------------------------------------------------
extern "C" void kernel_launch(void* const* d_in, const int* in_sizes, int n_in,
                              void* d_out, int out_size)
{
    const float* x        = (const float*)d_in[0];
    const float* enc_o    = (const float*)d_in[1];
    const int*   enc_mask = (const int*)  d_in[2];
    const float* a1_wq = (const float*)d_in[3];
    const float* a1_bq = (const float*)d_in[4];
    const float* a1_wk = (const float*)d_in[5];
    const float* a1_bk = (const float*)d_in[6];
    const float* a1_wv = (const float*)d_in[7];
    const float* a1_bv = (const float*)d_in[8];
    const float* a1_wo = (const float*)d_in[9];
    const float* a1_bo = (const float*)d_in[10];
    const float* a2_wq = (const float*)d_in[11];
    const float* a2_bq = (const float*)d_in[12];
    const float* a2_wk = (const float*)d_in[13];
    const float* a2_bk = (const float*)d_in[14];
    const float* a2_wv = (const float*)d_in[15];
    const float* a2_bv = (const float*)d_in[16];
    const float* a2_wo = (const float*)d_in[17];
    const float* a2_bo = (const float*)d_in[18];
    const float* ff_w1 = (const float*)d_in[19];
    const float* ff_b1 = (const float*)d_in[20];
    const float* ff_w2 = (const float*)d_in[21];
    const float* ff_b2 = (const float*)d_in[22];
    const float* ln1_g = (const float*)d_in[23];
    const float* ln1_b = (const float*)d_in[24];
    const float* ln2_g = (const float*)d_in[25];
    const float* ln2_b = (const float*)d_in[26];
    const float* ln3_g = (const float*)d_in[27];
    const float* ln3_b = (const float*)d_in[28];

    float* out_x    = (float*)d_out;
    float* out_attn = out_x + (size_t)cB*cSQ*cD;

    float *bufQ, *bufK, *bufV, *bufK2, *bufV2, *bufC, *bufO, *bufX1, *bufX2, *bufF;
    cudaGetSymbolAddress((void**)&bufQ,  g_bufQ);
    cudaGetSymbolAddress((void**)&bufK,  g_bufK);
    cudaGetSymbolAddress((void**)&bufV,  g_bufV);
    cudaGetSymbolAddress((void**)&bufK2, g_bufK2);
    cudaGetSymbolAddress((void**)&bufV2, g_bufV2);
    cudaGetSymbolAddress((void**)&bufC,  g_bufC);
    cudaGetSymbolAddress((void**)&bufO,  g_bufO);
    cudaGetSymbolAddress((void**)&bufX1, g_bufX1);
    cudaGetSymbolAddress((void**)&bufX2, g_bufX2);
    cudaGetSymbolAddress((void**)&bufF,  g_bufF);

    if (g_s2 == nullptr) {
        cudaStreamCreateWithFlags(&g_s2, cudaStreamNonBlocking);
        cudaEventCreateWithFlags(&g_evFork, cudaEventDisableTiming);
        cudaEventCreateWithFlags(&g_evJoin, cudaEventDisableTiming);
    }

    cudaFuncSetAttribute(attn_self_fused,
                         cudaFuncAttributeMaxDynamicSharedMemorySize, SMEM_SELF);
    cudaFuncSetAttribute(attn_cross_fused,
                         cudaFuncAttributeMaxDynamicSharedMemorySize, SMEM_CROSS);

    const float scale = 0.125f;   // 1/sqrt(64)
    const dim3 blk(256);
    const int M1 = cB * cSQ;      // 4096
    const int M2 = cB * cSK;      // 8192

    // ---- fork: cross K/V projection (depends only on enc_o) on side stream
    cudaEventRecord(g_evFork, 0);
    cudaStreamWaitEvent(g_s2, g_evFork, 0);
    gemm_fp16<false><<<dim3(cD/128, M2/128, 2), blk, 0, g_s2>>>(
        enc_o, mkset(a2_wk, a2_bk, bufK2, a2_wv, a2_bv, bufV2), M2, cD, cD);
    cudaEventRecord(g_evJoin, g_s2);

    // ---- main stream: self-attention block ----
    gemm_fp16<false><<<dim3(cD/128, M1/128, 3), blk>>>(
        x, mkset(a1_wq, a1_bq, bufQ, a1_wk, a1_bk, bufK, a1_wv, a1_bv, bufV),
        M1, cD, cD);
    attn_self_fused<<<dim3(cSQ/64, cB*cH), blk, SMEM_SELF>>>(
        bufQ, bufK, bufV, bufC, scale);
    gemm_fp16<false><<<dim3(cD/128, M1/128, 1), blk>>>(
        bufC, mkset(a1_wo, a1_bo, bufO), M1, cD, cD);
    ln_residual_kernel<<<M1, blk>>>(x, bufO, ln1_g, ln1_b, bufX1);

    // ---- cross-attention block ----
    gemm_fp16<false><<<dim3(cD/128, M1/128, 1), blk>>>(
        bufX1, mkset(a2_wq, a2_bq, bufQ), M1, cD, cD);
    cudaStreamWaitEvent(0, g_evJoin, 0);    // join side stream
    attn_cross_fused<<<dim3(cSQ/32, cB*cH), blk, SMEM_CROSS>>>(
        bufQ, bufK2, bufV2, enc_mask, out_attn, bufC, scale);
    gemm_fp16<false><<<dim3(cD/128, M1/128, 1), blk>>>(
        bufC, mkset(a2_wo, a2_bo, bufO), M1, cD, cD);
    ln_residual_kernel<<<M1, blk>>>(bufX1, bufO, ln2_g, ln2_b, bufX2);

    // ---- feed-forward ----
    gemm_fp16<true ><<<dim3(cF/128, M1/128, 1), blk>>>(
        bufX2, mkset(ff_w1, ff_b1, bufF), M1, cF, cD);
    gemm_fp16<false><<<dim3(cD/128, M1/128, 1), blk>>>(
        bufF, mkset(ff_w2, ff_b2, bufO), M1, cD, cF);
    ln_residual_kernel<<<M1, blk>>>(bufX2, bufO, ln3_g, ln3_b, out_x);
}